// round 2
// baseline (speedup 1.0000x reference)
#include <cuda_runtime.h>
#include <cuda_bf16.h>

#define NN 50000
#define NE 600000
#define F  128
#define NT 4
#define KTOT (5*F)   // 640
#define NROWS (NT*NN)  // 200000

typedef unsigned long long ull;

// ---------------- scratch (static device globals; no allocation) ------------
__device__ float g_s[(size_t)NT * NN * F];   // per-type neighbor means
__device__ int   g_cnt[NROWS];               // per-(type,dst) in-degree
__device__ int   g_off[NROWS];               // exclusive CSR offsets
__device__ int   g_cursor[NROWS];            // fill cursors
__device__ int   g_esrc[NE];                 // bucketed source indices
__device__ float g_h1[(size_t)NN * F];       // hidden activations after layer 1
__device__ float g_W1[KTOT * F];             // [Wself_bar ; Wn/4 x 4]
__device__ float g_W2[KTOT * F];
__device__ float g_bb1[F];
__device__ float g_bb2[F];

// ---------------- weight prep: fold type-mean into weights ------------------
__global__ void prep_weights(const float* __restrict__ Ws1, const float* __restrict__ Wn1,
                             const float* __restrict__ b1,
                             const float* __restrict__ Ws2, const float* __restrict__ Wn2,
                             const float* __restrict__ b2) {
    int idx = blockIdx.x * blockDim.x + threadIdx.x;   // over KTOT*F = 81920
    if (idx >= KTOT * F) return;
    int k = idx / F, j = idx % F;
    float w1, w2;
    if (k < F) {
        float a1 = 0.f, a2 = 0.f;
        #pragma unroll
        for (int t = 0; t < NT; t++) {
            a1 += Ws1[(t * F + k) * F + j];
            a2 += Ws2[(t * F + k) * F + j];
        }
        w1 = a1 * 0.25f; w2 = a2 * 0.25f;
    } else {
        int t = (k - F) >> 7;
        int kk = (k - F) & 127;
        w1 = Wn1[(t * F + kk) * F + j] * 0.25f;
        w2 = Wn2[(t * F + kk) * F + j] * 0.25f;
    }
    g_W1[idx] = w1; g_W2[idx] = w2;
    if (idx < F) {
        float s1 = 0.f, s2 = 0.f;
        #pragma unroll
        for (int t = 0; t < NT; t++) { s1 += b1[t * F + idx]; s2 += b2[t * F + idx]; }
        g_bb1[idx] = s1 * 0.25f; g_bb2[idx] = s2 * 0.25f;
    }
}

// ---------------- CSR build ---------------------------------------------------
__global__ void count_edges(const int* __restrict__ ei, const int* __restrict__ et) {
    int e = blockIdx.x * blockDim.x + threadIdx.x;
    if (e >= NE) return;
    atomicAdd(&g_cnt[et[e] * NN + ei[NE + e]], 1);
}

// single-block scan over 200000 counts -> exclusive offsets + cursors
__global__ void scan_offsets() {
    __shared__ int wsum[32];
    __shared__ int s_carry;
    int tid = threadIdx.x, lane = tid & 31, w = tid >> 5;
    if (tid == 0) s_carry = 0;
    __syncthreads();
    for (int base = 0; base < NROWS; base += 1024) {
        int idx = base + tid;
        int v = (idx < NROWS) ? g_cnt[idx] : 0;
        int x = v;
        #pragma unroll
        for (int o = 1; o < 32; o <<= 1) {
            int y = __shfl_up_sync(0xFFFFFFFFu, x, o);
            if (lane >= o) x += y;
        }
        if (lane == 31) wsum[w] = x;
        __syncthreads();
        if (w == 0) {
            int s = wsum[lane];
            #pragma unroll
            for (int o = 1; o < 32; o <<= 1) {
                int y = __shfl_up_sync(0xFFFFFFFFu, s, o);
                if (lane >= o) s += y;
            }
            wsum[lane] = s;
        }
        __syncthreads();
        int excl = x - v + (w > 0 ? wsum[w - 1] : 0) + s_carry;
        if (idx < NROWS) { g_off[idx] = excl; g_cursor[idx] = excl; }
        __syncthreads();
        if (tid == 0) s_carry += wsum[31];
        __syncthreads();
    }
}

__global__ void fill_edges(const int* __restrict__ ei, const int* __restrict__ et) {
    int e = blockIdx.x * blockDim.x + threadIdx.x;
    if (e >= NE) return;
    int src = ei[e];
    int dst = ei[NE + e];
    int t = et[e];
    int pos = atomicAdd(&g_cursor[t * NN + dst], 1);
    g_esrc[pos] = src;
}

// ---------------- neighbor means, no atomics: one warp per (t,node) row -------
__global__ void aggregate(const float* __restrict__ h) {
    int gtid = blockIdx.x * blockDim.x + threadIdx.x;
    int row = gtid >> 5;
    int lane = threadIdx.x & 31;
    if (row >= NROWS) return;
    int beg = g_off[row];
    int c = g_cnt[row];
    float4 acc = make_float4(0.f, 0.f, 0.f, 0.f);
    for (int i = 0; i < c; i++) {
        int s = __ldg(&g_esrc[beg + i]);
        float4 v = *reinterpret_cast<const float4*>(h + (size_t)s * F + lane * 4);
        acc.x += v.x; acc.y += v.y; acc.z += v.z; acc.w += v.w;
    }
    float inv = 1.0f / (float)(c > 1 ? c : 1);
    acc.x *= inv; acc.y *= inv; acc.z *= inv; acc.w *= inv;
    *(reinterpret_cast<float4*>(g_s + (size_t)row * F) + lane) = acc;
}

// ---------------- GEMM: out[N,128] = [h | means] (N x 640) @ W (640 x 128) ----
// Block tile 64x128, BK=16, 256 threads, thread tile 4x8, packed f32x2 FMA.
__device__ __forceinline__ void fma2(ull& d, ull a, ull b) {
    asm volatile("fma.rn.f32x2 %0, %1, %2, %0;" : "+l"(d) : "l"(a), "l"(b));
}

template <bool NORM>
__global__ __launch_bounds__(256)
void gemm_640(const float* __restrict__ A0, const float* __restrict__ W,
              const float* __restrict__ bias, float* __restrict__ out) {
    __shared__ float2 As2[16][64];   // [k][m], each element duplicated (a,a)
    __shared__ float  Bs[16][128];   // [k][n]

    int m0 = blockIdx.x * 64;
    int tid = threadIdx.x;
    int tr = tid >> 4;          // 0..15 -> rows tr*4 .. tr*4+3
    int tc = tid & 15;          // 0..15 -> cols tc*8 .. tc*8+7

    // A-load mapping: 64 rows x 16 k per tile; thread loads one float4
    int rowA = tid >> 2;               // 0..63
    int kvA  = (tid & 3) * 4;          // 0,4,8,12
    int n = m0 + rowA;
    bool valid = (n < NN);

    // B-load mapping: 16 rows x 128 cols; thread loads rows rB and rB+8
    int rB = tid >> 5;                 // 0..7
    int cB = (tid & 31) * 4;           // 0..124

    ull accp[4][4];
    #pragma unroll
    for (int i = 0; i < 4; i++)
        #pragma unroll
        for (int j = 0; j < 4; j++) accp[i][j] = 0ULL;

    for (int kk = 0; kk < KTOT; kk += 16) {
        // A tile source: segment 0 = A0 (h), segments 1..4 = means in g_s
        int seg  = kk >> 7;
        int koff = kk & 127;
        const float* arow = (seg == 0)
            ? (A0 + (size_t)n * F)
            : (g_s + ((size_t)((seg - 1) * NN + n)) * F);
        float4 av = make_float4(0.f, 0.f, 0.f, 0.f);
        if (valid) av = *reinterpret_cast<const float4*>(arow + koff + kvA);
        As2[kvA + 0][rowA] = make_float2(av.x, av.x);
        As2[kvA + 1][rowA] = make_float2(av.y, av.y);
        As2[kvA + 2][rowA] = make_float2(av.z, av.z);
        As2[kvA + 3][rowA] = make_float2(av.w, av.w);

        float4 b0 = *reinterpret_cast<const float4*>(W + (size_t)(kk + rB) * F + cB);
        float4 b1 = *reinterpret_cast<const float4*>(W + (size_t)(kk + rB + 8) * F + cB);
        *reinterpret_cast<float4*>(&Bs[rB][cB])     = b0;
        *reinterpret_cast<float4*>(&Bs[rB + 8][cB]) = b1;

        __syncthreads();

        #pragma unroll
        for (int k = 0; k < 16; k++) {
            ulonglong2 aa0 = *reinterpret_cast<const ulonglong2*>(&As2[k][tr * 4]);
            ulonglong2 aa1 = *reinterpret_cast<const ulonglong2*>(&As2[k][tr * 4 + 2]);
            ulonglong2 bb0 = *reinterpret_cast<const ulonglong2*>(&Bs[k][tc * 8]);
            ulonglong2 bb1 = *reinterpret_cast<const ulonglong2*>(&Bs[k][tc * 8 + 4]);
            ull a_[4] = {aa0.x, aa0.y, aa1.x, aa1.y};
            ull b_[4] = {bb0.x, bb0.y, bb1.x, bb1.y};
            #pragma unroll
            for (int i = 0; i < 4; i++)
                #pragma unroll
                for (int j = 0; j < 4; j++)
                    fma2(accp[i][j], a_[i], b_[j]);
        }
        __syncthreads();
    }

    // epilogue: + bias, (optional l2norm+relu), store
    float bb[8];
    #pragma unroll
    for (int j = 0; j < 8; j++) bb[j] = bias[tc * 8 + j];

    #pragma unroll
    for (int i = 0; i < 4; i++) {
        int row = m0 + tr * 4 + i;
        float v[8];
        #pragma unroll
        for (int j = 0; j < 4; j++) {
            float2 f = *reinterpret_cast<float2*>(&accp[i][j]);
            v[2 * j]     = f.x + bb[2 * j];
            v[2 * j + 1] = f.y + bb[2 * j + 1];
        }
        if (NORM) {
            float ss = 0.f;
            #pragma unroll
            for (int j = 0; j < 8; j++) ss += v[j] * v[j];
            // reduce across the 16 lanes sharing this output row (same half-warp)
            #pragma unroll
            for (int o = 1; o < 16; o <<= 1)
                ss += __shfl_xor_sync(0xFFFFFFFFu, ss, o);
            float inv = 1.0f / fmaxf(sqrtf(ss), 1e-12f);
            #pragma unroll
            for (int j = 0; j < 8; j++) v[j] = fmaxf(v[j] * inv, 0.f);
        }
        if (row < NN) {
            float4 o0 = make_float4(v[0], v[1], v[2], v[3]);
            float4 o1 = make_float4(v[4], v[5], v[6], v[7]);
            *reinterpret_cast<float4*>(out + (size_t)row * F + tc * 8)     = o0;
            *reinterpret_cast<float4*>(out + (size_t)row * F + tc * 8 + 4) = o1;
        }
    }
}

// ---------------- launch -------------------------------------------------------
extern "C" void kernel_launch(void* const* d_in, const int* in_sizes, int n_in,
                              void* d_out, int out_size) {
    const float* x   = (const float*)d_in[0];
    const float* Ws1 = (const float*)d_in[1];
    const float* Wn1 = (const float*)d_in[2];
    const float* b1  = (const float*)d_in[3];
    const float* Ws2 = (const float*)d_in[4];
    const float* Wn2 = (const float*)d_in[5];
    const float* b2  = (const float*)d_in[6];
    const int*   ei  = (const int*)d_in[7];
    const int*   et  = (const int*)d_in[8];
    float* out = (float*)d_out;

    void *p_h1, *p_W1, *p_W2, *p_bb1, *p_bb2, *p_cnt;
    cudaGetSymbolAddress(&p_h1, g_h1);
    cudaGetSymbolAddress(&p_W1, g_W1);
    cudaGetSymbolAddress(&p_W2, g_W2);
    cudaGetSymbolAddress(&p_bb1, g_bb1);
    cudaGetSymbolAddress(&p_bb2, g_bb2);
    cudaGetSymbolAddress(&p_cnt, g_cnt);

    const int AG_BLOCKS = (int)(((size_t)NROWS * 32 + 255) / 256);
    const int GM_BLOCKS = (NN + 63) / 64;

    // CSR build (counts/offsets layer-invariant)
    cudaMemsetAsync(p_cnt, 0, NROWS * sizeof(int));
    count_edges<<<(NE + 255) / 256, 256>>>(ei, et);
    scan_offsets<<<1, 1024>>>();
    fill_edges<<<(NE + 255) / 256, 256>>>(ei, et);
    prep_weights<<<(KTOT * F + 255) / 256, 256>>>(Ws1, Wn1, b1, Ws2, Wn2, b2);

    // ---- layer 1 ----
    aggregate<<<AG_BLOCKS, 256>>>(x);
    gemm_640<true><<<GM_BLOCKS, 256>>>(x, (const float*)p_W1, (const float*)p_bb1, (float*)p_h1);

    // ---- layer 2 ----
    aggregate<<<AG_BLOCKS, 256>>>((const float*)p_h1);
    gemm_640<false><<<GM_BLOCKS, 256>>>((const float*)p_h1, (const float*)p_W2, (const float*)p_bb2, out);
}

// round 3
// speedup vs baseline: 1.8000x; 1.8000x over previous
#include <cuda_runtime.h>
#include <cuda_bf16.h>

#define NN 50000
#define NE 600000
#define F  128
#define NT 4
#define NOUT 640      // [self(128) | Y_t(128)*4]

typedef unsigned long long ull;

// ---------------- scratch (static device globals; no allocation) ------------
__device__ float g_Y[(size_t)NN * NOUT];     // projected features per node
__device__ int   g_cnt[NT * NN];             // per-(type,dst) in-degree
__device__ int   g_off[NN];                  // exclusive CSR offsets (per dst)
__device__ int   g_cursor[NN];               // fill cursors (end = off + deg)
__device__ int   g_epk[NE];                  // packed (src<<2)|type, bucketed by dst
__device__ float g_h1[(size_t)NN * F];       // layer-1 output
__device__ float g_W1[F * NOUT];             // [Wself_bar | 0.25*Wn_t], [k][640]
__device__ float g_W2[F * NOUT];
__device__ float g_bb1[F];
__device__ float g_bb2[F];

// ---------------- weight prep -------------------------------------------------
__global__ void prep_weights(const float* __restrict__ Ws1, const float* __restrict__ Wn1,
                             const float* __restrict__ b1,
                             const float* __restrict__ Ws2, const float* __restrict__ Wn2,
                             const float* __restrict__ b2) {
    int idx = blockIdx.x * blockDim.x + threadIdx.x;   // over F*NOUT = 81920
    if (idx >= F * NOUT) return;
    int k = idx / NOUT, j = idx % NOUT;
    float w1, w2;
    if (j < F) {
        float a1 = 0.f, a2 = 0.f;
        #pragma unroll
        for (int t = 0; t < NT; t++) {
            a1 += Ws1[(t * F + k) * F + j];
            a2 += Ws2[(t * F + k) * F + j];
        }
        w1 = a1 * 0.25f; w2 = a2 * 0.25f;
    } else {
        int t  = (j - F) >> 7;
        int jj = (j - F) & 127;
        w1 = Wn1[(t * F + k) * F + jj] * 0.25f;
        w2 = Wn2[(t * F + k) * F + jj] * 0.25f;
    }
    g_W1[idx] = w1; g_W2[idx] = w2;
    if (idx < F) {
        float s1 = 0.f, s2 = 0.f;
        #pragma unroll
        for (int t = 0; t < NT; t++) { s1 += b1[t * F + idx]; s2 += b2[t * F + idx]; }
        g_bb1[idx] = s1 * 0.25f; g_bb2[idx] = s2 * 0.25f;
    }
}

// ---------------- CSR build ---------------------------------------------------
__global__ void zero_cnt() {
    int i = blockIdx.x * blockDim.x + threadIdx.x;
    if (i < NT * NN) g_cnt[i] = 0;
}

__global__ void count_edges(const int* __restrict__ ei, const int* __restrict__ et) {
    int e = blockIdx.x * blockDim.x + threadIdx.x;
    if (e >= NE) return;
    atomicAdd(&g_cnt[et[e] * NN + ei[NE + e]], 1);
}

// single-block exclusive scan over per-dst total degree
__global__ void scan_offsets() {
    __shared__ int wsum[32];
    __shared__ int s_carry;
    int tid = threadIdx.x, lane = tid & 31, w = tid >> 5;
    if (tid == 0) s_carry = 0;
    __syncthreads();
    for (int base = 0; base < NN; base += 1024) {
        int idx = base + tid;
        int v = 0;
        if (idx < NN) {
            #pragma unroll
            for (int t = 0; t < NT; t++) v += g_cnt[t * NN + idx];
        }
        int x = v;
        #pragma unroll
        for (int o = 1; o < 32; o <<= 1) {
            int y = __shfl_up_sync(0xFFFFFFFFu, x, o);
            if (lane >= o) x += y;
        }
        if (lane == 31) wsum[w] = x;
        __syncthreads();
        if (w == 0) {
            int s = wsum[lane];
            #pragma unroll
            for (int o = 1; o < 32; o <<= 1) {
                int y = __shfl_up_sync(0xFFFFFFFFu, s, o);
                if (lane >= o) s += y;
            }
            wsum[lane] = s;
        }
        __syncthreads();
        int excl = x - v + (w > 0 ? wsum[w - 1] : 0) + s_carry;
        if (idx < NN) { g_off[idx] = excl; g_cursor[idx] = excl; }
        __syncthreads();
        if (tid == 0) s_carry += wsum[31];
        __syncthreads();
    }
}

__global__ void fill_edges(const int* __restrict__ ei, const int* __restrict__ et) {
    int e = blockIdx.x * blockDim.x + threadIdx.x;
    if (e >= NE) return;
    int src = ei[e];
    int dst = ei[NE + e];
    int t = et[e];
    int pos = atomicAdd(&g_cursor[dst], 1);
    g_epk[pos] = (src << 2) | t;
}

// ---------------- GEMM: Y[N,640] = A[N,128] @ W[128,640] ----------------------
// 128x128 block tile, BK=32, 256 threads, 8x8 thread tile, f32x2 FMA.
#define BK 32

__device__ __forceinline__ void fma2(ull& d, ull a, ull b) {
    asm("fma.rn.f32x2 %0, %1, %2, %0;" : "+l"(d) : "l"(a), "l"(b));
}
__device__ __forceinline__ ull pack2(float a) {
    ull r;
    asm("mov.b64 %0, {%1, %1};" : "=l"(r) : "f"(a));
    return r;
}

__global__ __launch_bounds__(256)
void gemm_y(const float* __restrict__ A, const float* __restrict__ W,
            const float* __restrict__ bias, float* __restrict__ Y) {
    __shared__ float As[BK][128];   // [k][m]
    __shared__ float Bs[BK][128];   // [k][n]

    int m0 = blockIdx.x * 128;
    int n0 = blockIdx.y * 128;
    int tid = threadIdx.x;
    int tr = tid >> 4;          // 0..15 -> rows tr*8..tr*8+7
    int tc = tid & 15;          // 0..15 -> cols tc*8..tc*8+7

    // A load mapping: row = tid&127, k-quads (tid>>7)*4 + {0,8,16,24}
    int rowA = tid & 127;
    int kqA  = (tid >> 7) * 4;
    int grow = m0 + rowA;
    bool valid = (grow < NN);
    const float* arow = A + (size_t)grow * F;

    // B load mapping: rB = tid>>5 + {0,8,16,24}, cB = (tid&31)*4
    int rB = tid >> 5;
    int cB = (tid & 31) * 4;

    ull acc[8][4];
    #pragma unroll
    for (int i = 0; i < 8; i++)
        #pragma unroll
        for (int j = 0; j < 4; j++) acc[i][j] = 0ULL;

    for (int kt = 0; kt < F; kt += BK) {
        #pragma unroll
        for (int q = 0; q < 4; q++) {
            int kb = kqA + q * 8;   // 0..28
            float4 av = make_float4(0.f, 0.f, 0.f, 0.f);
            if (valid) av = *reinterpret_cast<const float4*>(arow + kt + kb);
            As[kb + 0][rowA] = av.x;
            As[kb + 1][rowA] = av.y;
            As[kb + 2][rowA] = av.z;
            As[kb + 3][rowA] = av.w;
        }
        #pragma unroll
        for (int q = 0; q < 4; q++) {
            int kb = rB + q * 8;
            float4 bv = *reinterpret_cast<const float4*>(W + (size_t)(kt + kb) * NOUT + n0 + cB);
            *reinterpret_cast<float4*>(&Bs[kb][cB]) = bv;
        }
        __syncthreads();

        #pragma unroll 8
        for (int k = 0; k < BK; k++) {
            float4 a0 = *reinterpret_cast<float4*>(&As[k][tr * 8]);
            float4 a1 = *reinterpret_cast<float4*>(&As[k][tr * 8 + 4]);
            ulonglong2 b0 = *reinterpret_cast<ulonglong2*>(&Bs[k][tc * 8]);
            ulonglong2 b1 = *reinterpret_cast<ulonglong2*>(&Bs[k][tc * 8 + 4]);
            ull bp[4] = {b0.x, b0.y, b1.x, b1.y};
            ull ap[8] = {pack2(a0.x), pack2(a0.y), pack2(a0.z), pack2(a0.w),
                         pack2(a1.x), pack2(a1.y), pack2(a1.z), pack2(a1.w)};
            #pragma unroll
            for (int i = 0; i < 8; i++)
                #pragma unroll
                for (int j = 0; j < 4; j++)
                    fma2(acc[i][j], ap[i], bp[j]);
        }
        __syncthreads();
    }

    // epilogue: bias only on the self block (n-tile 0, cols < 128)
    float bb[8];
    if (blockIdx.y == 0) {
        #pragma unroll
        for (int j = 0; j < 8; j++) bb[j] = bias[tc * 8 + j];
    } else {
        #pragma unroll
        for (int j = 0; j < 8; j++) bb[j] = 0.f;
    }

    #pragma unroll
    for (int i = 0; i < 8; i++) {
        int row = m0 + tr * 8 + i;
        if (row < NN) {
            float v[8];
            #pragma unroll
            for (int j = 0; j < 4; j++) {
                float2 f = *reinterpret_cast<float2*>(&acc[i][j]);
                v[2 * j]     = f.x + bb[2 * j];
                v[2 * j + 1] = f.y + bb[2 * j + 1];
            }
            float* orow = Y + (size_t)row * NOUT + n0 + tc * 8;
            *reinterpret_cast<float4*>(orow)     = make_float4(v[0], v[1], v[2], v[3]);
            *reinterpret_cast<float4*>(orow + 4) = make_float4(v[4], v[5], v[6], v[7]);
        }
    }
}

// ---------------- aggregate: out[dst] = Yself[dst] + sum_e invc[t]*Yt[src] ----
template <bool NORM>
__global__ void aggregate(float* __restrict__ outp) {
    int gtid = blockIdx.x * blockDim.x + threadIdx.x;
    int row = gtid >> 5;
    int lane = threadIdx.x & 31;
    if (row >= NN) return;

    float inv[NT];
    #pragma unroll
    for (int t = 0; t < NT; t++) {
        int c = __ldg(&g_cnt[t * NN + row]);
        inv[t] = 1.0f / (float)(c > 1 ? c : 1);
    }
    int beg = g_off[row];
    int end = g_cursor[row];   // after fill: off + degree

    float4 acc = *reinterpret_cast<const float4*>(g_Y + (size_t)row * NOUT + lane * 4);

    int i = beg;
    for (; i + 4 <= end; i += 4) {
        int pk0 = __ldg(&g_epk[i]);
        int pk1 = __ldg(&g_epk[i + 1]);
        int pk2 = __ldg(&g_epk[i + 2]);
        int pk3 = __ldg(&g_epk[i + 3]);
        const float4 v0 = *reinterpret_cast<const float4*>(
            g_Y + (size_t)(pk0 >> 2) * NOUT + ((pk0 & 3) + 1) * F + lane * 4);
        const float4 v1 = *reinterpret_cast<const float4*>(
            g_Y + (size_t)(pk1 >> 2) * NOUT + ((pk1 & 3) + 1) * F + lane * 4);
        const float4 v2 = *reinterpret_cast<const float4*>(
            g_Y + (size_t)(pk2 >> 2) * NOUT + ((pk2 & 3) + 1) * F + lane * 4);
        const float4 v3 = *reinterpret_cast<const float4*>(
            g_Y + (size_t)(pk3 >> 2) * NOUT + ((pk3 & 3) + 1) * F + lane * 4);
        float s0 = inv[pk0 & 3], s1 = inv[pk1 & 3], s2 = inv[pk2 & 3], s3 = inv[pk3 & 3];
        acc.x += s0 * v0.x; acc.y += s0 * v0.y; acc.z += s0 * v0.z; acc.w += s0 * v0.w;
        acc.x += s1 * v1.x; acc.y += s1 * v1.y; acc.z += s1 * v1.z; acc.w += s1 * v1.w;
        acc.x += s2 * v2.x; acc.y += s2 * v2.y; acc.z += s2 * v2.z; acc.w += s2 * v2.w;
        acc.x += s3 * v3.x; acc.y += s3 * v3.y; acc.z += s3 * v3.z; acc.w += s3 * v3.w;
    }
    for (; i < end; i++) {
        int pk = __ldg(&g_epk[i]);
        const float4 v = *reinterpret_cast<const float4*>(
            g_Y + (size_t)(pk >> 2) * NOUT + ((pk & 3) + 1) * F + lane * 4);
        float s = inv[pk & 3];
        acc.x += s * v.x; acc.y += s * v.y; acc.z += s * v.z; acc.w += s * v.w;
    }

    if (NORM) {
        float ss = acc.x * acc.x + acc.y * acc.y + acc.z * acc.z + acc.w * acc.w;
        #pragma unroll
        for (int o = 16; o > 0; o >>= 1)
            ss += __shfl_xor_sync(0xFFFFFFFFu, ss, o);
        float invn = 1.0f / fmaxf(sqrtf(ss), 1e-12f);
        acc.x = fmaxf(acc.x * invn, 0.f);
        acc.y = fmaxf(acc.y * invn, 0.f);
        acc.z = fmaxf(acc.z * invn, 0.f);
        acc.w = fmaxf(acc.w * invn, 0.f);
    }
    *(reinterpret_cast<float4*>(outp + (size_t)row * F) + lane) = acc;
}

// ---------------- launch -------------------------------------------------------
extern "C" void kernel_launch(void* const* d_in, const int* in_sizes, int n_in,
                              void* d_out, int out_size) {
    const float* x   = (const float*)d_in[0];
    const float* Ws1 = (const float*)d_in[1];
    const float* Wn1 = (const float*)d_in[2];
    const float* b1  = (const float*)d_in[3];
    const float* Ws2 = (const float*)d_in[4];
    const float* Wn2 = (const float*)d_in[5];
    const float* b2  = (const float*)d_in[6];
    const int*   ei  = (const int*)d_in[7];
    const int*   et  = (const int*)d_in[8];
    float* out = (float*)d_out;

    void *p_h1, *p_Y, *p_W1, *p_W2, *p_bb1, *p_bb2;
    cudaGetSymbolAddress(&p_h1, g_h1);
    cudaGetSymbolAddress(&p_Y, g_Y);
    cudaGetSymbolAddress(&p_W1, g_W1);
    cudaGetSymbolAddress(&p_W2, g_W2);
    cudaGetSymbolAddress(&p_bb1, g_bb1);
    cudaGetSymbolAddress(&p_bb2, g_bb2);

    dim3 gm_grid((NN + 127) / 128, NOUT / 128);   // 391 x 5
    const int AG_BLOCKS = (int)(((size_t)NN * 32 + 255) / 256);

    // launch order chosen so launch #6 (ncu -s 5 -c 1) is the layer-1 GEMM
    prep_weights<<<(F * NOUT + 255) / 256, 256>>>(Ws1, Wn1, b1, Ws2, Wn2, b2); // 1
    zero_cnt<<<(NT * NN + 255) / 256, 256>>>();                                 // 2
    count_edges<<<(NE + 255) / 256, 256>>>(ei, et);                             // 3
    scan_offsets<<<1, 1024>>>();                                                // 4
    fill_edges<<<(NE + 255) / 256, 256>>>(ei, et);                              // 5

    // ---- layer 1 ----
    gemm_y<<<gm_grid, 256>>>(x, (const float*)p_W1, (const float*)p_bb1, (float*)p_Y); // 6
    aggregate<true><<<AG_BLOCKS, 256>>>((float*)p_h1);                          // 7

    // ---- layer 2 ----
    gemm_y<<<gm_grid, 256>>>((const float*)p_h1, (const float*)p_W2,
                             (const float*)p_bb2, (float*)p_Y);                 // 8
    aggregate<false><<<AG_BLOCKS, 256>>>(out);                                  // 9
}

// round 5
// speedup vs baseline: 3.1612x; 1.7562x over previous
#include <cuda_runtime.h>
#include <cuda_bf16.h>
#include <cstdint>

#define NN 50000
#define NE 600000
#define F  128
#define NT 4
#define NOUT 640        // [self(128) | Y_t(128)*4]
#define RS 136          // padded smem row stride (bf16 elems)

typedef unsigned long long ull;

// ---------------- scratch (static device globals; no allocation) ------------
__device__ float g_Y[(size_t)NN * NOUT];       // projected features per node
__device__ int   g_cnt[NT * NN];               // per-(type,dst) in-degree
__device__ int   g_off[NN];                    // exclusive CSR offsets (per dst)
__device__ int   g_cursor[NN];                 // fill cursors (end = off + deg)
__device__ int   g_epk[NE];                    // packed (src<<2)|type, bucketed by dst
__device__ int   g_bsum[64];                   // block sums for scan
__device__ float g_h1[(size_t)NN * F];         // layer-1 output
__device__ __nv_bfloat16 g_Ahi[(size_t)NN * F];
__device__ __nv_bfloat16 g_Alo[(size_t)NN * F];
__device__ __nv_bfloat16 g_Whi1[NOUT * F];     // [n][k] layout (K-major rows)
__device__ __nv_bfloat16 g_Wlo1[NOUT * F];
__device__ __nv_bfloat16 g_Whi2[NOUT * F];
__device__ __nv_bfloat16 g_Wlo2[NOUT * F];
__device__ float g_bb1[F];
__device__ float g_bb2[F];

// ---------------- weight prep: fold type-mean, split to bf16 hi/lo ----------
__global__ void prep_weights(const float* __restrict__ Ws1, const float* __restrict__ Wn1,
                             const float* __restrict__ b1,
                             const float* __restrict__ Ws2, const float* __restrict__ Wn2,
                             const float* __restrict__ b2) {
    int idx = blockIdx.x * blockDim.x + threadIdx.x;   // over NOUT*F = 81920
    if (idx >= NOUT * F) return;
    int j = idx / F, k = idx % F;    // output col j, input k  (stored [j][k])
    float w1, w2;
    if (j < F) {
        float a1 = 0.f, a2 = 0.f;
        #pragma unroll
        for (int t = 0; t < NT; t++) {
            a1 += Ws1[(t * F + k) * F + j];
            a2 += Ws2[(t * F + k) * F + j];
        }
        w1 = a1 * 0.25f; w2 = a2 * 0.25f;
    } else {
        int t  = (j - F) >> 7;
        int jj = (j - F) & 127;
        w1 = Wn1[(t * F + k) * F + jj] * 0.25f;
        w2 = Wn2[(t * F + k) * F + jj] * 0.25f;
    }
    __nv_bfloat16 h1 = __float2bfloat16_rn(w1);
    __nv_bfloat16 h2 = __float2bfloat16_rn(w2);
    g_Whi1[idx] = h1; g_Wlo1[idx] = __float2bfloat16_rn(w1 - __bfloat162float(h1));
    g_Whi2[idx] = h2; g_Wlo2[idx] = __float2bfloat16_rn(w2 - __bfloat162float(h2));
    if (idx < F) {
        float s1 = 0.f, s2 = 0.f;
        #pragma unroll
        for (int t = 0; t < NT; t++) { s1 += b1[t * F + idx]; s2 += b2[t * F + idx]; }
        g_bb1[idx] = s1 * 0.25f; g_bb2[idx] = s2 * 0.25f;
    }
}

// ---------------- fp32 -> bf16 hi/lo conversion (activations) ----------------
__global__ void convert_bf16(const float* __restrict__ A) {
    size_t i = ((size_t)blockIdx.x * 256 + threadIdx.x) * 8;
    if (i >= (size_t)NN * F) return;
    float4 u0 = *reinterpret_cast<const float4*>(A + i);
    float4 u1 = *reinterpret_cast<const float4*>(A + i + 4);
    float f[8] = {u0.x, u0.y, u0.z, u0.w, u1.x, u1.y, u1.z, u1.w};
    uint32_t hw[4], lw[4];
    #pragma unroll
    for (int j = 0; j < 4; j++) {
        float a = f[2 * j], b = f[2 * j + 1];
        __nv_bfloat16 ha = __float2bfloat16_rn(a);
        __nv_bfloat16 hb = __float2bfloat16_rn(b);
        __nv_bfloat162 hp = __halves2bfloat162(ha, hb);
        __nv_bfloat162 lp = __floats2bfloat162_rn(a - __bfloat162float(ha),
                                                  b - __bfloat162float(hb));
        hw[j] = *reinterpret_cast<uint32_t*>(&hp);
        lw[j] = *reinterpret_cast<uint32_t*>(&lp);
    }
    *reinterpret_cast<uint4*>(g_Ahi + i) = make_uint4(hw[0], hw[1], hw[2], hw[3]);
    *reinterpret_cast<uint4*>(g_Alo + i) = make_uint4(lw[0], lw[1], lw[2], lw[3]);
}

// ---------------- CSR build ---------------------------------------------------
__global__ void zero_cnt() {
    int i = blockIdx.x * blockDim.x + threadIdx.x;
    if (i < NT * NN) g_cnt[i] = 0;
}
__global__ void count_edges(const int* __restrict__ ei, const int* __restrict__ et) {
    int e = blockIdx.x * blockDim.x + threadIdx.x;
    if (e >= NE) return;
    atomicAdd(&g_cnt[et[e] * NN + ei[NE + e]], 1);
}

// pass 1: per-block exclusive scan of total degree; block sums to g_bsum
__global__ void scan_blocks() {
    __shared__ int wsum[32];
    int tid = threadIdx.x, lane = tid & 31, w = tid >> 5;
    int idx = blockIdx.x * 1024 + tid;
    int v = 0;
    if (idx < NN) {
        #pragma unroll
        for (int t = 0; t < NT; t++) v += g_cnt[t * NN + idx];
    }
    int x = v;
    #pragma unroll
    for (int o = 1; o < 32; o <<= 1) {
        int y = __shfl_up_sync(0xFFFFFFFFu, x, o);
        if (lane >= o) x += y;
    }
    if (lane == 31) wsum[w] = x;
    __syncthreads();
    if (w == 0) {
        int s = wsum[lane];
        #pragma unroll
        for (int o = 1; o < 32; o <<= 1) {
            int y = __shfl_up_sync(0xFFFFFFFFu, s, o);
            if (lane >= o) s += y;
        }
        wsum[lane] = s;
    }
    __syncthreads();
    int excl = x - v + (w > 0 ? wsum[w - 1] : 0);
    if (idx < NN) g_off[idx] = excl;
    if (tid == 0) g_bsum[blockIdx.x] = wsum[31];
}
// pass 2: scan 49 block sums (one block of 64)
__global__ void scan_bsums() {
    __shared__ int s[64];
    int tid = threadIdx.x;
    s[tid] = (tid < 49) ? g_bsum[tid] : 0;
    __syncthreads();
    #pragma unroll
    for (int o = 1; o < 64; o <<= 1) {
        int v = (tid >= o) ? s[tid - o] : 0;
        __syncthreads();
        s[tid] += v;
        __syncthreads();
    }
    if (tid < 49) g_bsum[tid] = (tid > 0) ? s[tid - 1] : 0;
}
// pass 3: add block prefix; init cursors
__global__ void add_bsums() {
    int idx = blockIdx.x * 1024 + threadIdx.x;
    if (idx < NN) {
        int o = g_off[idx] + g_bsum[blockIdx.x];
        g_off[idx] = o;
        g_cursor[idx] = o;
    }
}

__global__ void fill_edges(const int* __restrict__ ei, const int* __restrict__ et) {
    int e = blockIdx.x * blockDim.x + threadIdx.x;
    if (e >= NE) return;
    int src = ei[e];
    int dst = ei[NE + e];
    int t = et[e];
    int pos = atomicAdd(&g_cursor[dst], 1);
    g_epk[pos] = (src << 2) | t;
}

// ---------------- mma.sync bf16 GEMM: Y[N,640] = A[N,128] @ W[128,640] --------
// Block 128Mx128N, full K=128 in smem; 8 warps, warp tile 32Mx64N.
// Markidis 3-pass: Ahi*Bhi + Ahi*Blo + Alo*Bhi, f32 accumulate.
__device__ __forceinline__ void mma_bf16(float* d, const uint32_t* a, const uint32_t* b) {
    asm volatile("mma.sync.aligned.m16n8k16.row.col.f32.bf16.bf16.f32 "
                 "{%0,%1,%2,%3}, {%4,%5,%6,%7}, {%8,%9}, {%0,%1,%2,%3};"
                 : "+f"(d[0]), "+f"(d[1]), "+f"(d[2]), "+f"(d[3])
                 : "r"(a[0]), "r"(a[1]), "r"(a[2]), "r"(a[3]),
                   "r"(b[0]), "r"(b[1]));
}

__device__ __forceinline__ void load_tile_pad(__nv_bfloat16* dhi, __nv_bfloat16* dlo,
                                              const __nv_bfloat16* __restrict__ ghi,
                                              const __nv_bfloat16* __restrict__ glo,
                                              int row0, int rlim) {
    int tid = threadIdx.x;
    #pragma unroll
    for (int i = 0; i < 8; i++) {
        int lin = tid + i * 256;     // 0..2047
        int r = lin >> 4, c = lin & 15;
        int gr = row0 + r;
        uint4 h = make_uint4(0, 0, 0, 0), l = make_uint4(0, 0, 0, 0);
        if (gr < rlim) {
            h = *reinterpret_cast<const uint4*>(ghi + (size_t)gr * F + c * 8);
            l = *reinterpret_cast<const uint4*>(glo + (size_t)gr * F + c * 8);
        }
        *reinterpret_cast<uint4*>(dhi + r * RS + c * 8) = h;
        *reinterpret_cast<uint4*>(dlo + r * RS + c * 8) = l;
    }
}

__global__ __launch_bounds__(256)
void gemm_tc(const __nv_bfloat16* __restrict__ whi, const __nv_bfloat16* __restrict__ wlo,
             const float* __restrict__ bias, float* __restrict__ Y) {
    extern __shared__ __nv_bfloat16 smem[];
    __nv_bfloat16* Ahi = smem;                  // 128 x RS
    __nv_bfloat16* Alo = Ahi + 128 * RS;
    __nv_bfloat16* Bhi = Alo + 128 * RS;
    __nv_bfloat16* Blo = Bhi + 128 * RS;

    int tid = threadIdx.x, wid = tid >> 5, lane = tid & 31;
    int gid = lane >> 2, tig = lane & 3;
    int wm = wid & 3, wn = wid >> 2;            // warp tile: rows wm*32.., cols wn*64..
    int m0 = blockIdx.x * 128;
    int n0 = blockIdx.y * 128;

    load_tile_pad(Ahi, Alo, g_Ahi, g_Alo, m0, NN);
    load_tile_pad(Bhi, Blo, whi, wlo, n0, NOUT);
    __syncthreads();

    float acc[2][8][4];
    #pragma unroll
    for (int i = 0; i < 2; i++)
        #pragma unroll
        for (int j = 0; j < 8; j++)
            #pragma unroll
            for (int q = 0; q < 4; q++) acc[i][j][q] = 0.f;

    int arow = wm * 32 + gid;      // + mf*16, +8 for a1/a3
    int brow = wn * 64 + gid;      // + nf*8

    #pragma unroll
    for (int ks = 0; ks < 8; ks++) {
        int kb = ks * 16 + tig * 2;

        uint32_t ah[2][4], al[2][4];
        #pragma unroll
        for (int mf = 0; mf < 2; mf++) {
            int r = arow + mf * 16;
            ah[mf][0] = *reinterpret_cast<const uint32_t*>(Ahi + r * RS + kb);
            ah[mf][1] = *reinterpret_cast<const uint32_t*>(Ahi + (r + 8) * RS + kb);
            ah[mf][2] = *reinterpret_cast<const uint32_t*>(Ahi + r * RS + kb + 8);
            ah[mf][3] = *reinterpret_cast<const uint32_t*>(Ahi + (r + 8) * RS + kb + 8);
            al[mf][0] = *reinterpret_cast<const uint32_t*>(Alo + r * RS + kb);
            al[mf][1] = *reinterpret_cast<const uint32_t*>(Alo + (r + 8) * RS + kb);
            al[mf][2] = *reinterpret_cast<const uint32_t*>(Alo + r * RS + kb + 8);
            al[mf][3] = *reinterpret_cast<const uint32_t*>(Alo + (r + 8) * RS + kb + 8);
        }
        uint32_t bh[8][2], bl[8][2];
        #pragma unroll
        for (int nf = 0; nf < 8; nf++) {
            int r = brow + nf * 8;
            bh[nf][0] = *reinterpret_cast<const uint32_t*>(Bhi + r * RS + kb);
            bh[nf][1] = *reinterpret_cast<const uint32_t*>(Bhi + r * RS + kb + 8);
            bl[nf][0] = *reinterpret_cast<const uint32_t*>(Blo + r * RS + kb);
            bl[nf][1] = *reinterpret_cast<const uint32_t*>(Blo + r * RS + kb + 8);
        }
        #pragma unroll
        for (int mf = 0; mf < 2; mf++)
            #pragma unroll
            for (int nf = 0; nf < 8; nf++) {
                mma_bf16(acc[mf][nf], ah[mf], bh[nf]);
                mma_bf16(acc[mf][nf], ah[mf], bl[nf]);
                mma_bf16(acc[mf][nf], al[mf], bh[nf]);
            }
    }

    // epilogue: bias only applies to output cols < 128 (blockIdx.y == 0)
    bool has_bias = (blockIdx.y == 0);
    #pragma unroll
    for (int nf = 0; nf < 8; nf++) {
        int col = wn * 64 + nf * 8 + tig * 2;    // within-tile col (== global col for y=0)
        float b0 = has_bias ? bias[col]     : 0.f;
        float b1 = has_bias ? bias[col + 1] : 0.f;
        #pragma unroll
        for (int mf = 0; mf < 2; mf++) {
            int row = m0 + wm * 32 + mf * 16 + gid;
            float* base = Y + (size_t)row * NOUT + n0 + col;
            if (row < NN) {
                *reinterpret_cast<float2*>(base) =
                    make_float2(acc[mf][nf][0] + b0, acc[mf][nf][1] + b1);
            }
            if (row + 8 < NN) {
                *reinterpret_cast<float2*>(base + 8 * NOUT) =
                    make_float2(acc[mf][nf][2] + b0, acc[mf][nf][3] + b1);
            }
        }
    }
}

// ---------------- aggregate: out[dst] = Yself[dst] + sum_e invc[t]*Yt[src] ----
template <bool NORM>
__global__ void aggregate(float* __restrict__ outp) {
    int gtid = blockIdx.x * blockDim.x + threadIdx.x;
    int row = gtid >> 5;
    int lane = threadIdx.x & 31;
    if (row >= NN) return;

    float inv[NT];
    #pragma unroll
    for (int t = 0; t < NT; t++) {
        int c = __ldg(&g_cnt[t * NN + row]);
        inv[t] = 1.0f / (float)(c > 1 ? c : 1);
    }
    int beg = g_off[row];
    int end = g_cursor[row];

    float4 acc = *reinterpret_cast<const float4*>(g_Y + (size_t)row * NOUT + lane * 4);

    int i = beg;
    for (; i + 4 <= end; i += 4) {
        int pk0 = __ldg(&g_epk[i]);
        int pk1 = __ldg(&g_epk[i + 1]);
        int pk2 = __ldg(&g_epk[i + 2]);
        int pk3 = __ldg(&g_epk[i + 3]);
        const float4 v0 = *reinterpret_cast<const float4*>(
            g_Y + (size_t)(pk0 >> 2) * NOUT + ((pk0 & 3) + 1) * F + lane * 4);
        const float4 v1 = *reinterpret_cast<const float4*>(
            g_Y + (size_t)(pk1 >> 2) * NOUT + ((pk1 & 3) + 1) * F + lane * 4);
        const float4 v2 = *reinterpret_cast<const float4*>(
            g_Y + (size_t)(pk2 >> 2) * NOUT + ((pk2 & 3) + 1) * F + lane * 4);
        const float4 v3 = *reinterpret_cast<const float4*>(
            g_Y + (size_t)(pk3 >> 2) * NOUT + ((pk3 & 3) + 1) * F + lane * 4);
        float s0 = inv[pk0 & 3], s1 = inv[pk1 & 3], s2 = inv[pk2 & 3], s3 = inv[pk3 & 3];
        acc.x += s0 * v0.x; acc.y += s0 * v0.y; acc.z += s0 * v0.z; acc.w += s0 * v0.w;
        acc.x += s1 * v1.x; acc.y += s1 * v1.y; acc.z += s1 * v1.z; acc.w += s1 * v1.w;
        acc.x += s2 * v2.x; acc.y += s2 * v2.y; acc.z += s2 * v2.z; acc.w += s2 * v2.w;
        acc.x += s3 * v3.x; acc.y += s3 * v3.y; acc.z += s3 * v3.z; acc.w += s3 * v3.w;
    }
    for (; i < end; i++) {
        int pk = __ldg(&g_epk[i]);
        const float4 v = *reinterpret_cast<const float4*>(
            g_Y + (size_t)(pk >> 2) * NOUT + ((pk & 3) + 1) * F + lane * 4);
        float s = inv[pk & 3];
        acc.x += s * v.x; acc.y += s * v.y; acc.z += s * v.z; acc.w += s * v.w;
    }

    if (NORM) {
        float ss = acc.x * acc.x + acc.y * acc.y + acc.z * acc.z + acc.w * acc.w;
        #pragma unroll
        for (int o = 16; o > 0; o >>= 1)
            ss += __shfl_xor_sync(0xFFFFFFFFu, ss, o);
        float invn = 1.0f / fmaxf(sqrtf(ss), 1e-12f);
        acc.x = fmaxf(acc.x * invn, 0.f);
        acc.y = fmaxf(acc.y * invn, 0.f);
        acc.z = fmaxf(acc.z * invn, 0.f);
        acc.w = fmaxf(acc.w * invn, 0.f);
    }
    *(reinterpret_cast<float4*>(outp + (size_t)row * F) + lane) = acc;
}

// ---------------- launch -------------------------------------------------------
extern "C" void kernel_launch(void* const* d_in, const int* in_sizes, int n_in,
                              void* d_out, int out_size) {
    const float* x   = (const float*)d_in[0];
    const float* Ws1 = (const float*)d_in[1];
    const float* Wn1 = (const float*)d_in[2];
    const float* b1  = (const float*)d_in[3];
    const float* Ws2 = (const float*)d_in[4];
    const float* Wn2 = (const float*)d_in[5];
    const float* b2  = (const float*)d_in[6];
    const int*   ei  = (const int*)d_in[7];
    const int*   et  = (const int*)d_in[8];
    float* out = (float*)d_out;

    void *p_h1, *p_Y, *p_bb1, *p_bb2, *p_Whi1, *p_Wlo1, *p_Whi2, *p_Wlo2;
    cudaGetSymbolAddress(&p_h1, g_h1);
    cudaGetSymbolAddress(&p_Y, g_Y);
    cudaGetSymbolAddress(&p_bb1, g_bb1);
    cudaGetSymbolAddress(&p_bb2, g_bb2);
    cudaGetSymbolAddress(&p_Whi1, g_Whi1);
    cudaGetSymbolAddress(&p_Wlo1, g_Wlo1);
    cudaGetSymbolAddress(&p_Whi2, g_Whi2);
    cudaGetSymbolAddress(&p_Wlo2, g_Wlo2);

    const int SMEM_GEMM = 4 * 128 * RS * sizeof(__nv_bfloat16);   // 139264
    cudaFuncSetAttribute(gemm_tc, cudaFuncAttributeMaxDynamicSharedMemorySize, SMEM_GEMM);

    dim3 gemm_grid((NN + 127) / 128, NOUT / 128);   // 391 x 5
    const int AG_BLOCKS = (int)(((size_t)NN * 32 + 255) / 256);
    const int SCAN_BLOCKS = (NN + 1023) / 1024;     // 49
    const int CV_BLOCKS = (int)(((size_t)NN * F / 8 + 255) / 256);

    prep_weights<<<(NOUT * F + 255) / 256, 256>>>(Ws1, Wn1, b1, Ws2, Wn2, b2);  // 1
    convert_bf16<<<CV_BLOCKS, 256>>>(x);                                        // 2
    zero_cnt<<<(NT * NN + 255) / 256, 256>>>();                                 // 3
    count_edges<<<(NE + 255) / 256, 256>>>(ei, et);                             // 4
    scan_blocks<<<SCAN_BLOCKS, 1024>>>();                                       // 5
    gemm_tc<<<gemm_grid, 256, SMEM_GEMM>>>((const __nv_bfloat16*)p_Whi1,        // 6 <- profiled
                                           (const __nv_bfloat16*)p_Wlo1,
                                           (const float*)p_bb1, (float*)p_Y);
    scan_bsums<<<1, 64>>>();                                                    // 7
    add_bsums<<<SCAN_BLOCKS, 1024>>>();                                         // 8
    fill_edges<<<(NE + 255) / 256, 256>>>(ei, et);                              // 9
    aggregate<true><<<AG_BLOCKS, 256>>>((float*)p_h1);                          // 10

    // ---- layer 2 ----
    convert_bf16<<<CV_BLOCKS, 256>>>((const float*)p_h1);                       // 11
    gemm_tc<<<gemm_grid, 256, SMEM_GEMM>>>((const __nv_bfloat16*)p_Whi2,        // 12
                                           (const __nv_bfloat16*)p_Wlo2,
                                           (const float*)p_bb2, (float*)p_Y);
    aggregate<false><<<AG_BLOCKS, 256>>>(out);                                  // 13
}

// round 6
// speedup vs baseline: 3.2496x; 1.0280x over previous
#include <cuda_runtime.h>
#include <cuda_bf16.h>
#include <cstdint>

#define NN 50000
#define NE 600000
#define F  128
#define NT 4
#define NOUT 640        // [self(128) | Y_t(128)*4]
#define RS 136          // padded smem row stride (bf16 elems)

typedef unsigned long long ull;

// ---------------- scratch (static device globals; no allocation) ------------
__device__ float g_Y[(size_t)NN * NOUT];       // projected features per node
__device__ int   g_cnt[NT * NN];               // per-(type,dst) in-degree
__device__ int   g_off[NN];                    // exclusive CSR offsets (per dst)
__device__ int   g_cursor[NN];                 // fill cursors (end = off + deg)
__device__ int   g_epk[NE];                    // packed (src<<2)|type, bucketed by dst
__device__ int   g_bsum[64];                   // block sums for scan
__device__ __nv_bfloat16 g_Ahi[(size_t)NN * F];
__device__ __nv_bfloat16 g_Alo[(size_t)NN * F];
__device__ __nv_bfloat16 g_Whi1[NOUT * F];     // [n][k] layout (K-major rows)
__device__ __nv_bfloat16 g_Wlo1[NOUT * F];
__device__ __nv_bfloat16 g_Whi2[NOUT * F];
__device__ __nv_bfloat16 g_Wlo2[NOUT * F];
__device__ float g_bb1[F];
__device__ float g_bb2[F];

// ---------------- weight prep: fold type-mean, split to bf16 hi/lo ----------
__global__ void prep_weights(const float* __restrict__ Ws1, const float* __restrict__ Wn1,
                             const float* __restrict__ b1,
                             const float* __restrict__ Ws2, const float* __restrict__ Wn2,
                             const float* __restrict__ b2) {
    int idx = blockIdx.x * blockDim.x + threadIdx.x;   // over NOUT*F = 81920
    if (idx >= NOUT * F) return;
    int j = idx / F, k = idx % F;    // output col j, input k  (stored [j][k])
    float w1, w2;
    if (j < F) {
        float a1 = 0.f, a2 = 0.f;
        #pragma unroll
        for (int t = 0; t < NT; t++) {
            a1 += Ws1[(t * F + k) * F + j];
            a2 += Ws2[(t * F + k) * F + j];
        }
        w1 = a1 * 0.25f; w2 = a2 * 0.25f;
    } else {
        int t  = (j - F) >> 7;
        int jj = (j - F) & 127;
        w1 = Wn1[(t * F + k) * F + jj] * 0.25f;
        w2 = Wn2[(t * F + k) * F + jj] * 0.25f;
    }
    __nv_bfloat16 h1 = __float2bfloat16_rn(w1);
    __nv_bfloat16 h2 = __float2bfloat16_rn(w2);
    g_Whi1[idx] = h1; g_Wlo1[idx] = __float2bfloat16_rn(w1 - __bfloat162float(h1));
    g_Whi2[idx] = h2; g_Wlo2[idx] = __float2bfloat16_rn(w2 - __bfloat162float(h2));
    if (idx < F) {
        float s1 = 0.f, s2 = 0.f;
        #pragma unroll
        for (int t = 0; t < NT; t++) { s1 += b1[t * F + idx]; s2 += b2[t * F + idx]; }
        g_bb1[idx] = s1 * 0.25f; g_bb2[idx] = s2 * 0.25f;
    }
}

// ---------------- fp32 -> bf16 hi/lo conversion (x only) ---------------------
__global__ void convert_bf16(const float* __restrict__ A) {
    size_t i = ((size_t)blockIdx.x * 256 + threadIdx.x) * 8;
    if (i >= (size_t)NN * F) return;
    float4 u0 = *reinterpret_cast<const float4*>(A + i);
    float4 u1 = *reinterpret_cast<const float4*>(A + i + 4);
    float f[8] = {u0.x, u0.y, u0.z, u0.w, u1.x, u1.y, u1.z, u1.w};
    uint32_t hw[4], lw[4];
    #pragma unroll
    for (int j = 0; j < 4; j++) {
        float a = f[2 * j], b = f[2 * j + 1];
        __nv_bfloat16 ha = __float2bfloat16_rn(a);
        __nv_bfloat16 hb = __float2bfloat16_rn(b);
        __nv_bfloat162 hp = __halves2bfloat162(ha, hb);
        __nv_bfloat162 lp = __floats2bfloat162_rn(a - __bfloat162float(ha),
                                                  b - __bfloat162float(hb));
        hw[j] = *reinterpret_cast<uint32_t*>(&hp);
        lw[j] = *reinterpret_cast<uint32_t*>(&lp);
    }
    *reinterpret_cast<uint4*>(g_Ahi + i) = make_uint4(hw[0], hw[1], hw[2], hw[3]);
    *reinterpret_cast<uint4*>(g_Alo + i) = make_uint4(lw[0], lw[1], lw[2], lw[3]);
}

// ---------------- CSR build ---------------------------------------------------
__global__ void zero_cnt() {
    int i = blockIdx.x * blockDim.x + threadIdx.x;
    if (i < NT * NN) g_cnt[i] = 0;
}
__global__ void count_edges(const int* __restrict__ ei, const int* __restrict__ et) {
    int e = blockIdx.x * blockDim.x + threadIdx.x;
    if (e >= NE) return;
    atomicAdd(&g_cnt[et[e] * NN + ei[NE + e]], 1);
}

__global__ void scan_blocks() {
    __shared__ int wsum[32];
    int tid = threadIdx.x, lane = tid & 31, w = tid >> 5;
    int idx = blockIdx.x * 1024 + tid;
    int v = 0;
    if (idx < NN) {
        #pragma unroll
        for (int t = 0; t < NT; t++) v += g_cnt[t * NN + idx];
    }
    int x = v;
    #pragma unroll
    for (int o = 1; o < 32; o <<= 1) {
        int y = __shfl_up_sync(0xFFFFFFFFu, x, o);
        if (lane >= o) x += y;
    }
    if (lane == 31) wsum[w] = x;
    __syncthreads();
    if (w == 0) {
        int s = wsum[lane];
        #pragma unroll
        for (int o = 1; o < 32; o <<= 1) {
            int y = __shfl_up_sync(0xFFFFFFFFu, s, o);
            if (lane >= o) s += y;
        }
        wsum[lane] = s;
    }
    __syncthreads();
    int excl = x - v + (w > 0 ? wsum[w - 1] : 0);
    if (idx < NN) g_off[idx] = excl;
    if (tid == 0) g_bsum[blockIdx.x] = wsum[31];
}
__global__ void scan_bsums() {
    __shared__ int s[64];
    int tid = threadIdx.x;
    s[tid] = (tid < 49) ? g_bsum[tid] : 0;
    __syncthreads();
    #pragma unroll
    for (int o = 1; o < 64; o <<= 1) {
        int v = (tid >= o) ? s[tid - o] : 0;
        __syncthreads();
        s[tid] += v;
        __syncthreads();
    }
    if (tid < 49) g_bsum[tid] = (tid > 0) ? s[tid - 1] : 0;
}
__global__ void add_bsums() {
    int idx = blockIdx.x * 1024 + threadIdx.x;
    if (idx < NN) {
        int o = g_off[idx] + g_bsum[blockIdx.x];
        g_off[idx] = o;
        g_cursor[idx] = o;
    }
}

__global__ void fill_edges(const int* __restrict__ ei, const int* __restrict__ et) {
    int e = blockIdx.x * blockDim.x + threadIdx.x;
    if (e >= NE) return;
    int src = ei[e];
    int dst = ei[NE + e];
    int t = et[e];
    int pos = atomicAdd(&g_cursor[dst], 1);
    g_epk[pos] = (src << 2) | t;
}

// ---------------- mma.sync bf16 GEMM: Y[N,640] = A[N,128] @ W[128,640] --------
// Block 128Mx128N, full K=128 in smem; 8 warps, warp tile 32Mx64N.
// Markidis 3-pass: Ahi*Bhi + Ahi*Blo + Alo*Bhi, f32 accumulate. ldmatrix loads.
__device__ __forceinline__ void mma_bf16(float* d, const uint32_t* a, const uint32_t* b) {
    asm volatile("mma.sync.aligned.m16n8k16.row.col.f32.bf16.bf16.f32 "
                 "{%0,%1,%2,%3}, {%4,%5,%6,%7}, {%8,%9}, {%0,%1,%2,%3};"
                 : "+f"(d[0]), "+f"(d[1]), "+f"(d[2]), "+f"(d[3])
                 : "r"(a[0]), "r"(a[1]), "r"(a[2]), "r"(a[3]),
                   "r"(b[0]), "r"(b[1]));
}
__device__ __forceinline__ void ldsm_x4(uint32_t* r, uint32_t saddr) {
    asm volatile("ldmatrix.sync.aligned.m8n8.x4.shared.b16 {%0,%1,%2,%3}, [%4];"
                 : "=r"(r[0]), "=r"(r[1]), "=r"(r[2]), "=r"(r[3]) : "r"(saddr));
}

__device__ __forceinline__ void load_tile_pad(__nv_bfloat16* dhi, __nv_bfloat16* dlo,
                                              const __nv_bfloat16* __restrict__ ghi,
                                              const __nv_bfloat16* __restrict__ glo,
                                              int row0, int rlim) {
    int tid = threadIdx.x;
    #pragma unroll
    for (int i = 0; i < 8; i++) {
        int lin = tid + i * 256;     // 0..2047
        int r = lin >> 4, c = lin & 15;
        int gr = row0 + r;
        uint4 h = make_uint4(0, 0, 0, 0), l = make_uint4(0, 0, 0, 0);
        if (gr < rlim) {
            h = *reinterpret_cast<const uint4*>(ghi + (size_t)gr * F + c * 8);
            l = *reinterpret_cast<const uint4*>(glo + (size_t)gr * F + c * 8);
        }
        *reinterpret_cast<uint4*>(dhi + r * RS + c * 8) = h;
        *reinterpret_cast<uint4*>(dlo + r * RS + c * 8) = l;
    }
}

__global__ __launch_bounds__(256)
void gemm_tc(const __nv_bfloat16* __restrict__ whi, const __nv_bfloat16* __restrict__ wlo,
             const float* __restrict__ bias, float* __restrict__ Y) {
    extern __shared__ __nv_bfloat16 smem[];
    __nv_bfloat16* Ahi = smem;                  // 128 x RS
    __nv_bfloat16* Alo = Ahi + 128 * RS;
    __nv_bfloat16* Bhi = Alo + 128 * RS;
    __nv_bfloat16* Blo = Bhi + 128 * RS;

    int tid = threadIdx.x, wid = tid >> 5, lane = tid & 31;
    int gid = lane >> 2, tig = lane & 3;
    int l8 = lane & 7, sel = lane >> 3;         // ldmatrix address roles
    int wm = wid & 3, wn = wid >> 2;            // warp tile: rows wm*32.., cols wn*64..
    int m0 = blockIdx.x * 128;
    int n0 = blockIdx.y * 128;

    load_tile_pad(Ahi, Alo, g_Ahi, g_Alo, m0, NN);
    load_tile_pad(Bhi, Blo, whi, wlo, n0, NOUT);
    __syncthreads();

    uint32_t sAhi = (uint32_t)__cvta_generic_to_shared(Ahi);
    uint32_t sAlo = (uint32_t)__cvta_generic_to_shared(Alo);
    uint32_t sBhi = (uint32_t)__cvta_generic_to_shared(Bhi);
    uint32_t sBlo = (uint32_t)__cvta_generic_to_shared(Blo);

    float acc[2][8][4];
    #pragma unroll
    for (int i = 0; i < 2; i++)
        #pragma unroll
        for (int j = 0; j < 8; j++)
            #pragma unroll
            for (int q = 0; q < 4; q++) acc[i][j][q] = 0.f;

    // ldmatrix lane-address offsets (elements):
    // A x4 (m16k16 at row ar, col kb): matrices {r,k}: {ar+l8,kb},{ar+8+l8,kb},{ar+l8,kb+8},{ar+8+l8,kb+8}
    int a_r = (sel & 1) * 8 + l8;     // row offset within 16
    int a_k = (sel >> 1) * 8;         // k offset within 16
    // B x4 (16n x 16k at row nb, col kb): {nb+l8,kb},{nb+l8,kb+8},{nb+8+l8,kb},{nb+8+l8,kb+8}
    int b_n = (sel >> 1) * 8 + l8;
    int b_k = (sel & 1) * 8;

    #pragma unroll
    for (int ks = 0; ks < 8; ks++) {
        int kb = ks * 16;

        uint32_t ah[2][4], al[2][4];
        #pragma unroll
        for (int mf = 0; mf < 2; mf++) {
            uint32_t off = (uint32_t)(((wm * 32 + mf * 16 + a_r) * RS + kb + a_k) * 2);
            ldsm_x4(ah[mf], sAhi + off);
            ldsm_x4(al[mf], sAlo + off);
        }
        uint32_t bh[4][4], bl[4][4];
        #pragma unroll
        for (int g = 0; g < 4; g++) {
            uint32_t off = (uint32_t)(((wn * 64 + g * 16 + b_n) * RS + kb + b_k) * 2);
            ldsm_x4(bh[g], sBhi + off);
            ldsm_x4(bl[g], sBlo + off);
        }
        #pragma unroll
        for (int mf = 0; mf < 2; mf++)
            #pragma unroll
            for (int g = 0; g < 4; g++) {
                // nf = g*2 : regs {[0],[1]};  nf = g*2+1 : regs {[2],[3]}
                mma_bf16(acc[mf][g * 2],     ah[mf], &bh[g][0]);
                mma_bf16(acc[mf][g * 2],     ah[mf], &bl[g][0]);
                mma_bf16(acc[mf][g * 2],     al[mf], &bh[g][0]);
                mma_bf16(acc[mf][g * 2 + 1], ah[mf], &bh[g][2]);
                mma_bf16(acc[mf][g * 2 + 1], ah[mf], &bl[g][2]);
                mma_bf16(acc[mf][g * 2 + 1], al[mf], &bh[g][2]);
            }
    }

    // epilogue: bias only applies to output cols < 128 (blockIdx.y == 0)
    bool has_bias = (blockIdx.y == 0);
    #pragma unroll
    for (int nf = 0; nf < 8; nf++) {
        int col = wn * 64 + nf * 8 + tig * 2;
        float b0 = has_bias ? bias[col]     : 0.f;
        float b1 = has_bias ? bias[col + 1] : 0.f;
        #pragma unroll
        for (int mf = 0; mf < 2; mf++) {
            int row = m0 + wm * 32 + mf * 16 + gid;
            float* base = Y + (size_t)row * NOUT + n0 + col;
            if (row < NN) {
                *reinterpret_cast<float2*>(base) =
                    make_float2(acc[mf][nf][0] + b0, acc[mf][nf][1] + b1);
            }
            if (row + 8 < NN) {
                *reinterpret_cast<float2*>(base + 8 * NOUT) =
                    make_float2(acc[mf][nf][2] + b0, acc[mf][nf][3] + b1);
            }
        }
    }
}

// ---------------- aggregate: out[dst] = Yself[dst] + sum_e invc[t]*Yt[src] ----
// NORM=true: l2norm+relu, then write bf16 hi/lo (layer-2 GEMM input) directly.
template <bool NORM>
__global__ void aggregate(float* __restrict__ outp) {
    int gtid = blockIdx.x * blockDim.x + threadIdx.x;
    int row = gtid >> 5;
    int lane = threadIdx.x & 31;
    if (row >= NN) return;

    float inv[NT];
    #pragma unroll
    for (int t = 0; t < NT; t++) {
        int c = __ldg(&g_cnt[t * NN + row]);
        inv[t] = 1.0f / (float)(c > 1 ? c : 1);
    }
    int beg = g_off[row];
    int end = g_cursor[row];

    float4 acc = *reinterpret_cast<const float4*>(g_Y + (size_t)row * NOUT + lane * 4);

    int i = beg;
    for (; i + 4 <= end; i += 4) {
        int pk0 = __ldg(&g_epk[i]);
        int pk1 = __ldg(&g_epk[i + 1]);
        int pk2 = __ldg(&g_epk[i + 2]);
        int pk3 = __ldg(&g_epk[i + 3]);
        const float4 v0 = *reinterpret_cast<const float4*>(
            g_Y + (size_t)(pk0 >> 2) * NOUT + ((pk0 & 3) + 1) * F + lane * 4);
        const float4 v1 = *reinterpret_cast<const float4*>(
            g_Y + (size_t)(pk1 >> 2) * NOUT + ((pk1 & 3) + 1) * F + lane * 4);
        const float4 v2 = *reinterpret_cast<const float4*>(
            g_Y + (size_t)(pk2 >> 2) * NOUT + ((pk2 & 3) + 1) * F + lane * 4);
        const float4 v3 = *reinterpret_cast<const float4*>(
            g_Y + (size_t)(pk3 >> 2) * NOUT + ((pk3 & 3) + 1) * F + lane * 4);
        float s0 = inv[pk0 & 3], s1 = inv[pk1 & 3], s2 = inv[pk2 & 3], s3 = inv[pk3 & 3];
        acc.x += s0 * v0.x; acc.y += s0 * v0.y; acc.z += s0 * v0.z; acc.w += s0 * v0.w;
        acc.x += s1 * v1.x; acc.y += s1 * v1.y; acc.z += s1 * v1.z; acc.w += s1 * v1.w;
        acc.x += s2 * v2.x; acc.y += s2 * v2.y; acc.z += s2 * v2.z; acc.w += s2 * v2.w;
        acc.x += s3 * v3.x; acc.y += s3 * v3.y; acc.z += s3 * v3.z; acc.w += s3 * v3.w;
    }
    for (; i < end; i++) {
        int pk = __ldg(&g_epk[i]);
        const float4 v = *reinterpret_cast<const float4*>(
            g_Y + (size_t)(pk >> 2) * NOUT + ((pk & 3) + 1) * F + lane * 4);
        float s = inv[pk & 3];
        acc.x += s * v.x; acc.y += s * v.y; acc.z += s * v.z; acc.w += s * v.w;
    }

    if (NORM) {
        float ss = acc.x * acc.x + acc.y * acc.y + acc.z * acc.z + acc.w * acc.w;
        #pragma unroll
        for (int o = 16; o > 0; o >>= 1)
            ss += __shfl_xor_sync(0xFFFFFFFFu, ss, o);
        float invn = 1.0f / fmaxf(sqrtf(ss), 1e-12f);
        acc.x = fmaxf(acc.x * invn, 0.f);
        acc.y = fmaxf(acc.y * invn, 0.f);
        acc.z = fmaxf(acc.z * invn, 0.f);
        acc.w = fmaxf(acc.w * invn, 0.f);
        // fused bf16 hi/lo split (layer-2 GEMM input); h1 fp32 never materialized
        float f[4] = {acc.x, acc.y, acc.z, acc.w};
        uint32_t hw[2], lw[2];
        #pragma unroll
        for (int j = 0; j < 2; j++) {
            float a = f[2 * j], b = f[2 * j + 1];
            __nv_bfloat16 ha = __float2bfloat16_rn(a);
            __nv_bfloat16 hb = __float2bfloat16_rn(b);
            __nv_bfloat162 hp = __halves2bfloat162(ha, hb);
            __nv_bfloat162 lp = __floats2bfloat162_rn(a - __bfloat162float(ha),
                                                      b - __bfloat162float(hb));
            hw[j] = *reinterpret_cast<uint32_t*>(&hp);
            lw[j] = *reinterpret_cast<uint32_t*>(&lp);
        }
        size_t o = (size_t)row * F + lane * 4;
        *reinterpret_cast<uint2*>(g_Ahi + o) = make_uint2(hw[0], hw[1]);
        *reinterpret_cast<uint2*>(g_Alo + o) = make_uint2(lw[0], lw[1]);
    } else {
        *(reinterpret_cast<float4*>(outp + (size_t)row * F) + lane) = acc;
    }
}

// ---------------- launch -------------------------------------------------------
extern "C" void kernel_launch(void* const* d_in, const int* in_sizes, int n_in,
                              void* d_out, int out_size) {
    const float* x   = (const float*)d_in[0];
    const float* Ws1 = (const float*)d_in[1];
    const float* Wn1 = (const float*)d_in[2];
    const float* b1  = (const float*)d_in[3];
    const float* Ws2 = (const float*)d_in[4];
    const float* Wn2 = (const float*)d_in[5];
    const float* b2  = (const float*)d_in[6];
    const int*   ei  = (const int*)d_in[7];
    const int*   et  = (const int*)d_in[8];
    float* out = (float*)d_out;

    void *p_Y, *p_bb1, *p_bb2, *p_Whi1, *p_Wlo1, *p_Whi2, *p_Wlo2;
    cudaGetSymbolAddress(&p_Y, g_Y);
    cudaGetSymbolAddress(&p_bb1, g_bb1);
    cudaGetSymbolAddress(&p_bb2, g_bb2);
    cudaGetSymbolAddress(&p_Whi1, g_Whi1);
    cudaGetSymbolAddress(&p_Wlo1, g_Wlo1);
    cudaGetSymbolAddress(&p_Whi2, g_Whi2);
    cudaGetSymbolAddress(&p_Wlo2, g_Wlo2);

    const int SMEM_GEMM = 4 * 128 * RS * sizeof(__nv_bfloat16);   // 139264
    cudaFuncSetAttribute(gemm_tc, cudaFuncAttributeMaxDynamicSharedMemorySize, SMEM_GEMM);

    dim3 gemm_grid((NN + 127) / 128, NOUT / 128);   // 391 x 5
    const int AG_BLOCKS = (int)(((size_t)NN * 32 + 255) / 256);
    const int SCAN_BLOCKS = (NN + 1023) / 1024;     // 49
    const int CV_BLOCKS = (int)(((size_t)NN * F / 8 + 255) / 256);

    prep_weights<<<(NOUT * F + 255) / 256, 256>>>(Ws1, Wn1, b1, Ws2, Wn2, b2);  // 1
    convert_bf16<<<CV_BLOCKS, 256>>>(x);                                        // 2
    zero_cnt<<<(NT * NN + 255) / 256, 256>>>();                                 // 3
    gemm_tc<<<gemm_grid, 256, SMEM_GEMM>>>((const __nv_bfloat16*)p_Whi1,        // 4 <- profiled
                                           (const __nv_bfloat16*)p_Wlo1,
                                           (const float*)p_bb1, (float*)p_Y);
    count_edges<<<(NE + 255) / 256, 256>>>(ei, et);                             // 5
    scan_blocks<<<SCAN_BLOCKS, 1024>>>();                                       // 6
    scan_bsums<<<1, 64>>>();                                                    // 7
    add_bsums<<<SCAN_BLOCKS, 1024>>>();                                         // 8
    fill_edges<<<(NE + 255) / 256, 256>>>(ei, et);                              // 9
    aggregate<true><<<AG_BLOCKS, 256>>>(nullptr);                               // 10 (writes Ahi/Alo)

    // ---- layer 2 ----
    gemm_tc<<<gemm_grid, 256, SMEM_GEMM>>>((const __nv_bfloat16*)p_Whi2,        // 11
                                           (const __nv_bfloat16*)p_Wlo2,
                                           (const float*)p_bb2, (float*)p_Y);
    aggregate<false><<<AG_BLOCKS, 256>>>(out);                                  // 12
}

// round 7
// speedup vs baseline: 3.2717x; 1.0068x over previous
#include <cuda_runtime.h>
#include <cuda_bf16.h>
#include <cstdint>

#define NN 50000
#define NE 600000
#define F  128
#define NT 4
#define NOUT 640        // [self(128) | Y_t(128)*4]
#define RS 136          // padded smem row stride (bf16 elems)
#define HALF_N 64
#define NHALF 10        // NOUT / HALF_N

typedef unsigned long long ull;

// ---------------- scratch (static device globals; no allocation) ------------
__device__ float g_Y[(size_t)NN * NOUT];       // projected features per node
__device__ int   g_cnt[NT * NN];               // per-(type,dst) in-degree
__device__ int   g_off[NN];                    // exclusive CSR offsets (per dst)
__device__ int   g_cursor[NN];                 // fill cursors (end = off + deg)
__device__ int   g_epk[NE];                    // packed (src<<2)|type, bucketed by dst
__device__ int   g_bsum[64];                   // block sums for scan
__device__ __nv_bfloat16 g_Ahi[(size_t)NN * F];
__device__ __nv_bfloat16 g_Alo[(size_t)NN * F];
__device__ __nv_bfloat16 g_Whi1[NOUT * F];     // [n][k] layout (K-major rows)
__device__ __nv_bfloat16 g_Wlo1[NOUT * F];
__device__ __nv_bfloat16 g_Whi2[NOUT * F];
__device__ __nv_bfloat16 g_Wlo2[NOUT * F];
__device__ float g_bb1[F];
__device__ float g_bb2[F];

// ---------------- weight prep: fold type-mean, split to bf16 hi/lo ----------
__global__ void prep_weights(const float* __restrict__ Ws1, const float* __restrict__ Wn1,
                             const float* __restrict__ b1,
                             const float* __restrict__ Ws2, const float* __restrict__ Wn2,
                             const float* __restrict__ b2) {
    int idx = blockIdx.x * blockDim.x + threadIdx.x;   // over NOUT*F = 81920
    if (idx >= NOUT * F) return;
    int j = idx / F, k = idx % F;    // output col j, input k  (stored [j][k])
    float w1, w2;
    if (j < F) {
        float a1 = 0.f, a2 = 0.f;
        #pragma unroll
        for (int t = 0; t < NT; t++) {
            a1 += Ws1[(t * F + k) * F + j];
            a2 += Ws2[(t * F + k) * F + j];
        }
        w1 = a1 * 0.25f; w2 = a2 * 0.25f;
    } else {
        int t  = (j - F) >> 7;
        int jj = (j - F) & 127;
        w1 = Wn1[(t * F + k) * F + jj] * 0.25f;
        w2 = Wn2[(t * F + k) * F + jj] * 0.25f;
    }
    __nv_bfloat16 h1 = __float2bfloat16_rn(w1);
    __nv_bfloat16 h2 = __float2bfloat16_rn(w2);
    g_Whi1[idx] = h1; g_Wlo1[idx] = __float2bfloat16_rn(w1 - __bfloat162float(h1));
    g_Whi2[idx] = h2; g_Wlo2[idx] = __float2bfloat16_rn(w2 - __bfloat162float(h2));
    if (idx < F) {
        float s1 = 0.f, s2 = 0.f;
        #pragma unroll
        for (int t = 0; t < NT; t++) { s1 += b1[t * F + idx]; s2 += b2[t * F + idx]; }
        g_bb1[idx] = s1 * 0.25f; g_bb2[idx] = s2 * 0.25f;
    }
}

// ---------------- fp32 -> bf16 hi/lo conversion (x only) ---------------------
__global__ void convert_bf16(const float* __restrict__ A) {
    size_t i = ((size_t)blockIdx.x * 256 + threadIdx.x) * 8;
    if (i >= (size_t)NN * F) return;
    float4 u0 = *reinterpret_cast<const float4*>(A + i);
    float4 u1 = *reinterpret_cast<const float4*>(A + i + 4);
    float f[8] = {u0.x, u0.y, u0.z, u0.w, u1.x, u1.y, u1.z, u1.w};
    uint32_t hw[4], lw[4];
    #pragma unroll
    for (int j = 0; j < 4; j++) {
        float a = f[2 * j], b = f[2 * j + 1];
        __nv_bfloat16 ha = __float2bfloat16_rn(a);
        __nv_bfloat16 hb = __float2bfloat16_rn(b);
        __nv_bfloat162 hp = __halves2bfloat162(ha, hb);
        __nv_bfloat162 lp = __floats2bfloat162_rn(a - __bfloat162float(ha),
                                                  b - __bfloat162float(hb));
        hw[j] = *reinterpret_cast<uint32_t*>(&hp);
        lw[j] = *reinterpret_cast<uint32_t*>(&lp);
    }
    *reinterpret_cast<uint4*>(g_Ahi + i) = make_uint4(hw[0], hw[1], hw[2], hw[3]);
    *reinterpret_cast<uint4*>(g_Alo + i) = make_uint4(lw[0], lw[1], lw[2], lw[3]);
}

// ---------------- CSR build ---------------------------------------------------
__global__ void zero_cnt() {
    int i = blockIdx.x * blockDim.x + threadIdx.x;
    if (i < NT * NN) g_cnt[i] = 0;
}
__global__ void count_edges(const int* __restrict__ ei, const int* __restrict__ et) {
    int e = blockIdx.x * blockDim.x + threadIdx.x;
    if (e >= NE) return;
    atomicAdd(&g_cnt[et[e] * NN + ei[NE + e]], 1);
}

__global__ void scan_blocks() {
    __shared__ int wsum[32];
    int tid = threadIdx.x, lane = tid & 31, w = tid >> 5;
    int idx = blockIdx.x * 1024 + tid;
    int v = 0;
    if (idx < NN) {
        #pragma unroll
        for (int t = 0; t < NT; t++) v += g_cnt[t * NN + idx];
    }
    int x = v;
    #pragma unroll
    for (int o = 1; o < 32; o <<= 1) {
        int y = __shfl_up_sync(0xFFFFFFFFu, x, o);
        if (lane >= o) x += y;
    }
    if (lane == 31) wsum[w] = x;
    __syncthreads();
    if (w == 0) {
        int s = wsum[lane];
        #pragma unroll
        for (int o = 1; o < 32; o <<= 1) {
            int y = __shfl_up_sync(0xFFFFFFFFu, s, o);
            if (lane >= o) s += y;
        }
        wsum[lane] = s;
    }
    __syncthreads();
    int excl = x - v + (w > 0 ? wsum[w - 1] : 0);
    if (idx < NN) g_off[idx] = excl;
    if (tid == 0) g_bsum[blockIdx.x] = wsum[31];
}
__global__ void scan_bsums() {
    __shared__ int s[64];
    int tid = threadIdx.x;
    s[tid] = (tid < 49) ? g_bsum[tid] : 0;
    __syncthreads();
    #pragma unroll
    for (int o = 1; o < 64; o <<= 1) {
        int v = (tid >= o) ? s[tid - o] : 0;
        __syncthreads();
        s[tid] += v;
        __syncthreads();
    }
    if (tid < 49) g_bsum[tid] = (tid > 0) ? s[tid - 1] : 0;
}
__global__ void add_bsums() {
    int idx = blockIdx.x * 1024 + threadIdx.x;
    if (idx < NN) {
        int o = g_off[idx] + g_bsum[blockIdx.x];
        g_off[idx] = o;
        g_cursor[idx] = o;
    }
}

__global__ void fill_edges(const int* __restrict__ ei, const int* __restrict__ et) {
    int e = blockIdx.x * blockDim.x + threadIdx.x;
    if (e >= NE) return;
    int src = ei[e];
    int dst = ei[NE + e];
    int t = et[e];
    int pos = atomicAdd(&g_cursor[dst], 1);
    g_epk[pos] = (src << 2) | t;
}

// ---------------- mma.sync bf16 GEMM: Y[N,640] = A[N,128] @ W[128,640] --------
// One CTA per 128-row M tile. A (hi/lo) resident in smem; B streamed in 64-col
// half-tiles, double-buffered with cp.async. Warp tile 32Mx32N, 8 warps.
// Markidis 3-pass: Ahi*Bhi + Ahi*Blo + Alo*Bhi, f32 accumulate.
__device__ __forceinline__ void mma_bf16(float* d, const uint32_t* a, const uint32_t* b) {
    asm volatile("mma.sync.aligned.m16n8k16.row.col.f32.bf16.bf16.f32 "
                 "{%0,%1,%2,%3}, {%4,%5,%6,%7}, {%8,%9}, {%0,%1,%2,%3};"
                 : "+f"(d[0]), "+f"(d[1]), "+f"(d[2]), "+f"(d[3])
                 : "r"(a[0]), "r"(a[1]), "r"(a[2]), "r"(a[3]),
                   "r"(b[0]), "r"(b[1]));
}
__device__ __forceinline__ void ldsm_x4(uint32_t* r, uint32_t saddr) {
    asm volatile("ldmatrix.sync.aligned.m8n8.x4.shared.b16 {%0,%1,%2,%3}, [%4];"
                 : "=r"(r[0]), "=r"(r[1]), "=r"(r[2]), "=r"(r[3]) : "r"(saddr));
}
__device__ __forceinline__ void cp16(void* dst, const void* src) {
    uint32_t d = (uint32_t)__cvta_generic_to_shared(dst);
    asm volatile("cp.async.cg.shared.global [%0], [%1], 16;" :: "r"(d), "l"(src));
}
#define CP_COMMIT() asm volatile("cp.async.commit_group;" ::: "memory")
#define CP_WAIT(n)  asm volatile("cp.async.wait_group %0;" :: "n"(n) : "memory")

__global__ __launch_bounds__(256)
void gemm_tc(const __nv_bfloat16* __restrict__ whi, const __nv_bfloat16* __restrict__ wlo,
             const float* __restrict__ bias, float* __restrict__ Y) {
    extern __shared__ __nv_bfloat16 smem[];
    __nv_bfloat16* Ahi = smem;                       // 128 x RS
    __nv_bfloat16* Alo = Ahi + 128 * RS;             // 128 x RS
    __nv_bfloat16* Bbuf = Alo + 128 * RS;            // 2 bufs x (hi 64xRS + lo 64xRS)

    int tid = threadIdx.x, wid = tid >> 5, lane = tid & 31;
    int gid = lane >> 2, tig = lane & 3;
    int l8 = lane & 7, sel = lane >> 3;
    int wm = wid & 3, wn = wid >> 2;                 // warp tile rows wm*32, cols wn*32
    int m0 = blockIdx.x * 128;

    // --- resident A tile (hi/lo), loaded once ---
    #pragma unroll
    for (int i = 0; i < 8; i++) {
        int lin = tid + i * 256;                     // 0..2047
        int r = lin >> 4, c = lin & 15;
        int gr = m0 + r;
        uint4 h = make_uint4(0, 0, 0, 0), l = make_uint4(0, 0, 0, 0);
        if (gr < NN) {
            h = *reinterpret_cast<const uint4*>(g_Ahi + (size_t)gr * F + c * 8);
            l = *reinterpret_cast<const uint4*>(g_Alo + (size_t)gr * F + c * 8);
        }
        *reinterpret_cast<uint4*>(Ahi + r * RS + c * 8) = h;
        *reinterpret_cast<uint4*>(Alo + r * RS + c * 8) = l;
    }

    // --- B prefetch helper: half-tile s into buffer buf ---
    auto issue_B = [&](int s, int buf) {
        const __nv_bfloat16* srch = whi + (size_t)s * HALF_N * F;
        const __nv_bfloat16* srcl = wlo + (size_t)s * HALF_N * F;
        __nv_bfloat16* dh = Bbuf + buf * 2 * HALF_N * RS;
        __nv_bfloat16* dl = dh + HALF_N * RS;
        #pragma unroll
        for (int i = 0; i < 4; i++) {
            int lin = tid + i * 256;                 // 0..1023
            int r = lin >> 4, c = lin & 15;
            cp16(dh + r * RS + c * 8, srch + r * F + c * 8);
            cp16(dl + r * RS + c * 8, srcl + r * F + c * 8);
        }
        CP_COMMIT();
    };

    issue_B(0, 0);

    uint32_t sAhi = (uint32_t)__cvta_generic_to_shared(Ahi);
    uint32_t sAlo = (uint32_t)__cvta_generic_to_shared(Alo);

    int a_r = (sel & 1) * 8 + l8;
    int a_k = (sel >> 1) * 8;
    int b_n = (sel >> 1) * 8 + l8;
    int b_k = (sel & 1) * 8;

    for (int s = 0; s < NHALF; s++) {
        int buf = s & 1;
        if (s + 1 < NHALF) {
            issue_B(s + 1, buf ^ 1);
            CP_WAIT(1);
        } else {
            CP_WAIT(0);
        }
        __syncthreads();

        uint32_t sBh = (uint32_t)__cvta_generic_to_shared(Bbuf + buf * 2 * HALF_N * RS);
        uint32_t sBl = sBh + HALF_N * RS * 2;

        float acc[2][4][4];
        #pragma unroll
        for (int i = 0; i < 2; i++)
            #pragma unroll
            for (int j = 0; j < 4; j++)
                #pragma unroll
                for (int q = 0; q < 4; q++) acc[i][j][q] = 0.f;

        #pragma unroll
        for (int ks = 0; ks < 8; ks++) {
            int kb = ks * 16;
            uint32_t ah[2][4], al[2][4];
            #pragma unroll
            for (int mf = 0; mf < 2; mf++) {
                uint32_t off = (uint32_t)(((wm * 32 + mf * 16 + a_r) * RS + kb + a_k) * 2);
                ldsm_x4(ah[mf], sAhi + off);
                ldsm_x4(al[mf], sAlo + off);
            }
            uint32_t bh[2][4], bl[2][4];
            #pragma unroll
            for (int g = 0; g < 2; g++) {
                uint32_t off = (uint32_t)(((wn * 32 + g * 16 + b_n) * RS + kb + b_k) * 2);
                ldsm_x4(bh[g], sBh + off);
                ldsm_x4(bl[g], sBl + off);
            }
            #pragma unroll
            for (int mf = 0; mf < 2; mf++)
                #pragma unroll
                for (int g = 0; g < 2; g++) {
                    mma_bf16(acc[mf][g * 2],     ah[mf], &bh[g][0]);
                    mma_bf16(acc[mf][g * 2],     ah[mf], &bl[g][0]);
                    mma_bf16(acc[mf][g * 2],     al[mf], &bh[g][0]);
                    mma_bf16(acc[mf][g * 2 + 1], ah[mf], &bh[g][2]);
                    mma_bf16(acc[mf][g * 2 + 1], ah[mf], &bl[g][2]);
                    mma_bf16(acc[mf][g * 2 + 1], al[mf], &bh[g][2]);
                }
        }

        // epilogue for this 64-col half: global cols s*64 .. s*64+63
        int gc0 = s * HALF_N;
        bool has_bias = (gc0 < F);
        #pragma unroll
        for (int nf = 0; nf < 4; nf++) {
            int gc = gc0 + wn * 32 + nf * 8 + tig * 2;
            float b0 = has_bias ? bias[gc]     : 0.f;
            float b1 = has_bias ? bias[gc + 1] : 0.f;
            #pragma unroll
            for (int mf = 0; mf < 2; mf++) {
                int row = m0 + wm * 32 + mf * 16 + gid;
                float* base = Y + (size_t)row * NOUT + gc;
                if (row < NN)
                    *reinterpret_cast<float2*>(base) =
                        make_float2(acc[mf][nf][0] + b0, acc[mf][nf][1] + b1);
                if (row + 8 < NN)
                    *reinterpret_cast<float2*>(base + 8 * NOUT) =
                        make_float2(acc[mf][nf][2] + b0, acc[mf][nf][3] + b1);
            }
        }
        __syncthreads();   // all warps done with buf before it is refilled (iter s+1 issues into buf^1; buf reused at s+2)
    }
}

// ---------------- aggregate: out[dst] = Yself[dst] + sum_e invc[t]*Yt[src] ----
// NORM=true: l2norm+relu, then write bf16 hi/lo (layer-2 GEMM input) directly.
template <bool NORM>
__global__ void aggregate(float* __restrict__ outp) {
    int gtid = blockIdx.x * blockDim.x + threadIdx.x;
    int row = gtid >> 5;
    int lane = threadIdx.x & 31;
    if (row >= NN) return;

    float inv[NT];
    #pragma unroll
    for (int t = 0; t < NT; t++) {
        int c = __ldg(&g_cnt[t * NN + row]);
        inv[t] = 1.0f / (float)(c > 1 ? c : 1);
    }
    int beg = g_off[row];
    int end = g_cursor[row];

    float4 acc = *reinterpret_cast<const float4*>(g_Y + (size_t)row * NOUT + lane * 4);

    int i = beg;
    for (; i + 4 <= end; i += 4) {
        int pk0 = __ldg(&g_epk[i]);
        int pk1 = __ldg(&g_epk[i + 1]);
        int pk2 = __ldg(&g_epk[i + 2]);
        int pk3 = __ldg(&g_epk[i + 3]);
        const float4 v0 = *reinterpret_cast<const float4*>(
            g_Y + (size_t)(pk0 >> 2) * NOUT + ((pk0 & 3) + 1) * F + lane * 4);
        const float4 v1 = *reinterpret_cast<const float4*>(
            g_Y + (size_t)(pk1 >> 2) * NOUT + ((pk1 & 3) + 1) * F + lane * 4);
        const float4 v2 = *reinterpret_cast<const float4*>(
            g_Y + (size_t)(pk2 >> 2) * NOUT + ((pk2 & 3) + 1) * F + lane * 4);
        const float4 v3 = *reinterpret_cast<const float4*>(
            g_Y + (size_t)(pk3 >> 2) * NOUT + ((pk3 & 3) + 1) * F + lane * 4);
        float s0 = inv[pk0 & 3], s1 = inv[pk1 & 3], s2 = inv[pk2 & 3], s3 = inv[pk3 & 3];
        acc.x += s0 * v0.x; acc.y += s0 * v0.y; acc.z += s0 * v0.z; acc.w += s0 * v0.w;
        acc.x += s1 * v1.x; acc.y += s1 * v1.y; acc.z += s1 * v1.z; acc.w += s1 * v1.w;
        acc.x += s2 * v2.x; acc.y += s2 * v2.y; acc.z += s2 * v2.z; acc.w += s2 * v2.w;
        acc.x += s3 * v3.x; acc.y += s3 * v3.y; acc.z += s3 * v3.z; acc.w += s3 * v3.w;
    }
    for (; i < end; i++) {
        int pk = __ldg(&g_epk[i]);
        const float4 v = *reinterpret_cast<const float4*>(
            g_Y + (size_t)(pk >> 2) * NOUT + ((pk & 3) + 1) * F + lane * 4);
        float s = inv[pk & 3];
        acc.x += s * v.x; acc.y += s * v.y; acc.z += s * v.z; acc.w += s * v.w;
    }

    if (NORM) {
        float ss = acc.x * acc.x + acc.y * acc.y + acc.z * acc.z + acc.w * acc.w;
        #pragma unroll
        for (int o = 16; o > 0; o >>= 1)
            ss += __shfl_xor_sync(0xFFFFFFFFu, ss, o);
        float invn = 1.0f / fmaxf(sqrtf(ss), 1e-12f);
        acc.x = fmaxf(acc.x * invn, 0.f);
        acc.y = fmaxf(acc.y * invn, 0.f);
        acc.z = fmaxf(acc.z * invn, 0.f);
        acc.w = fmaxf(acc.w * invn, 0.f);
        float f[4] = {acc.x, acc.y, acc.z, acc.w};
        uint32_t hw[2], lw[2];
        #pragma unroll
        for (int j = 0; j < 2; j++) {
            float a = f[2 * j], b = f[2 * j + 1];
            __nv_bfloat16 ha = __float2bfloat16_rn(a);
            __nv_bfloat16 hb = __float2bfloat16_rn(b);
            __nv_bfloat162 hp = __halves2bfloat162(ha, hb);
            __nv_bfloat162 lp = __floats2bfloat162_rn(a - __bfloat162float(ha),
                                                      b - __bfloat162float(hb));
            hw[j] = *reinterpret_cast<uint32_t*>(&hp);
            lw[j] = *reinterpret_cast<uint32_t*>(&lp);
        }
        size_t o = (size_t)row * F + lane * 4;
        *reinterpret_cast<uint2*>(g_Ahi + o) = make_uint2(hw[0], hw[1]);
        *reinterpret_cast<uint2*>(g_Alo + o) = make_uint2(lw[0], lw[1]);
    } else {
        *(reinterpret_cast<float4*>(outp + (size_t)row * F) + lane) = acc;
    }
}

// ---------------- launch -------------------------------------------------------
extern "C" void kernel_launch(void* const* d_in, const int* in_sizes, int n_in,
                              void* d_out, int out_size) {
    const float* x   = (const float*)d_in[0];
    const float* Ws1 = (const float*)d_in[1];
    const float* Wn1 = (const float*)d_in[2];
    const float* b1  = (const float*)d_in[3];
    const float* Ws2 = (const float*)d_in[4];
    const float* Wn2 = (const float*)d_in[5];
    const float* b2  = (const float*)d_in[6];
    const int*   ei  = (const int*)d_in[7];
    const int*   et  = (const int*)d_in[8];
    float* out = (float*)d_out;

    void *p_Y, *p_bb1, *p_bb2, *p_Whi1, *p_Wlo1, *p_Whi2, *p_Wlo2;
    cudaGetSymbolAddress(&p_Y, g_Y);
    cudaGetSymbolAddress(&p_bb1, g_bb1);
    cudaGetSymbolAddress(&p_bb2, g_bb2);
    cudaGetSymbolAddress(&p_Whi1, g_Whi1);
    cudaGetSymbolAddress(&p_Wlo1, g_Wlo1);
    cudaGetSymbolAddress(&p_Whi2, g_Whi2);
    cudaGetSymbolAddress(&p_Wlo2, g_Wlo2);

    // smem: A hi/lo (2*128*RS) + B double-buffered hi/lo halves (4*64*RS)
    const int SMEM_GEMM = (2 * 128 * RS + 4 * HALF_N * RS) * (int)sizeof(__nv_bfloat16);
    cudaFuncSetAttribute(gemm_tc, cudaFuncAttributeMaxDynamicSharedMemorySize, SMEM_GEMM);

    const int GM_BLOCKS = (NN + 127) / 128;         // 391
    const int AG_BLOCKS = (int)(((size_t)NN * 32 + 255) / 256);
    const int SCAN_BLOCKS = (NN + 1023) / 1024;     // 49
    const int CV_BLOCKS = (int)(((size_t)NN * F / 8 + 255) / 256);

    prep_weights<<<(NOUT * F + 255) / 256, 256>>>(Ws1, Wn1, b1, Ws2, Wn2, b2);  // 1
    convert_bf16<<<CV_BLOCKS, 256>>>(x);                                        // 2
    zero_cnt<<<(NT * NN + 255) / 256, 256>>>();                                 // 3
    gemm_tc<<<GM_BLOCKS, 256, SMEM_GEMM>>>((const __nv_bfloat16*)p_Whi1,        // 4 <- profiled
                                           (const __nv_bfloat16*)p_Wlo1,
                                           (const float*)p_bb1, (float*)p_Y);
    count_edges<<<(NE + 255) / 256, 256>>>(ei, et);                             // 5
    scan_blocks<<<SCAN_BLOCKS, 1024>>>();                                       // 6
    scan_bsums<<<1, 64>>>();                                                    // 7
    add_bsums<<<SCAN_BLOCKS, 1024>>>();                                         // 8
    fill_edges<<<(NE + 255) / 256, 256>>>(ei, et);                              // 9
    aggregate<true><<<AG_BLOCKS, 256>>>(nullptr);                               // 10 (writes Ahi/Alo)

    // ---- layer 2 ----
    gemm_tc<<<GM_BLOCKS, 256, SMEM_GEMM>>>((const __nv_bfloat16*)p_Whi2,        // 11
                                           (const __nv_bfloat16*)p_Wlo2,
                                           (const float*)p_bb2, (float*)p_Y);
    aggregate<false><<<AG_BLOCKS, 256>>>(out);                                  // 12
}

// round 8
// speedup vs baseline: 3.3456x; 1.0226x over previous
#include <cuda_runtime.h>
#include <cuda_bf16.h>
#include <cstdint>

#define NN 50000
#define NE 600000
#define F  128
#define NT 4
#define NOUT 640        // [self(128) | Y_t(128)*4]
#define RS 136          // padded smem row stride (bf16 elems)
#define HALF_N 64
#define NHALF 10        // NOUT / HALF_N

typedef unsigned long long ull;

// ---------------- scratch (static device globals; no allocation) ------------
__device__ float g_Y[(size_t)NN * NOUT];       // projected features per node
__device__ int   g_cnt[NT * NN];               // per-(type,dst) in-degree
__device__ int   g_off[NN];                    // exclusive CSR offsets (per dst)
__device__ int   g_cursor[NN];                 // fill cursors (end = off + deg)
__device__ int   g_epk[NE];                    // packed (src<<2)|type, bucketed by dst
__device__ int   g_bsum[64];                   // block sums for scan
__device__ __nv_bfloat16 g_Ahi[(size_t)NN * F];
__device__ __nv_bfloat16 g_Alo[(size_t)NN * F];
__device__ __nv_bfloat16 g_Whi1[NOUT * F];     // [n][k] layout (K-major rows)
__device__ __nv_bfloat16 g_Wlo1[NOUT * F];
__device__ __nv_bfloat16 g_Whi2[NOUT * F];
__device__ __nv_bfloat16 g_Wlo2[NOUT * F];
__device__ float g_bb1[F];
__device__ float g_bb2[F];

// ---------------- weight prep: fold type-mean, split to bf16 hi/lo ----------
__global__ void prep_weights(const float* __restrict__ Ws1, const float* __restrict__ Wn1,
                             const float* __restrict__ b1,
                             const float* __restrict__ Ws2, const float* __restrict__ Wn2,
                             const float* __restrict__ b2) {
    int idx = blockIdx.x * blockDim.x + threadIdx.x;   // over NOUT*F = 81920
    if (idx >= NOUT * F) return;
    int j = idx / F, k = idx % F;    // output col j, input k  (stored [j][k])
    float w1, w2;
    if (j < F) {
        float a1 = 0.f, a2 = 0.f;
        #pragma unroll
        for (int t = 0; t < NT; t++) {
            a1 += Ws1[(t * F + k) * F + j];
            a2 += Ws2[(t * F + k) * F + j];
        }
        w1 = a1 * 0.25f; w2 = a2 * 0.25f;
    } else {
        int t  = (j - F) >> 7;
        int jj = (j - F) & 127;
        w1 = Wn1[(t * F + k) * F + jj] * 0.25f;
        w2 = Wn2[(t * F + k) * F + jj] * 0.25f;
    }
    __nv_bfloat16 h1 = __float2bfloat16_rn(w1);
    __nv_bfloat16 h2 = __float2bfloat16_rn(w2);
    g_Whi1[idx] = h1; g_Wlo1[idx] = __float2bfloat16_rn(w1 - __bfloat162float(h1));
    g_Whi2[idx] = h2; g_Wlo2[idx] = __float2bfloat16_rn(w2 - __bfloat162float(h2));
    if (idx < F) {
        float s1 = 0.f, s2 = 0.f;
        #pragma unroll
        for (int t = 0; t < NT; t++) { s1 += b1[t * F + idx]; s2 += b2[t * F + idx]; }
        g_bb1[idx] = s1 * 0.25f; g_bb2[idx] = s2 * 0.25f;
    }
}

// ---------------- fp32 -> bf16 hi/lo conversion (x only) ---------------------
__global__ void convert_bf16(const float* __restrict__ A) {
    size_t i = ((size_t)blockIdx.x * 256 + threadIdx.x) * 8;
    if (i >= (size_t)NN * F) return;
    float4 u0 = *reinterpret_cast<const float4*>(A + i);
    float4 u1 = *reinterpret_cast<const float4*>(A + i + 4);
    float f[8] = {u0.x, u0.y, u0.z, u0.w, u1.x, u1.y, u1.z, u1.w};
    uint32_t hw[4], lw[4];
    #pragma unroll
    for (int j = 0; j < 4; j++) {
        float a = f[2 * j], b = f[2 * j + 1];
        __nv_bfloat16 ha = __float2bfloat16_rn(a);
        __nv_bfloat16 hb = __float2bfloat16_rn(b);
        __nv_bfloat162 hp = __halves2bfloat162(ha, hb);
        __nv_bfloat162 lp = __floats2bfloat162_rn(a - __bfloat162float(ha),
                                                  b - __bfloat162float(hb));
        hw[j] = *reinterpret_cast<uint32_t*>(&hp);
        lw[j] = *reinterpret_cast<uint32_t*>(&lp);
    }
    *reinterpret_cast<uint4*>(g_Ahi + i) = make_uint4(hw[0], hw[1], hw[2], hw[3]);
    *reinterpret_cast<uint4*>(g_Alo + i) = make_uint4(lw[0], lw[1], lw[2], lw[3]);
}

// ---------------- CSR build ---------------------------------------------------
__global__ void zero_cnt() {
    int i = blockIdx.x * blockDim.x + threadIdx.x;
    if (i < NT * NN) g_cnt[i] = 0;
}
__global__ void count_edges(const int* __restrict__ ei, const int* __restrict__ et) {
    int e = blockIdx.x * blockDim.x + threadIdx.x;
    if (e >= NE) return;
    atomicAdd(&g_cnt[et[e] * NN + ei[NE + e]], 1);
}

__global__ void scan_blocks() {
    __shared__ int wsum[32];
    int tid = threadIdx.x, lane = tid & 31, w = tid >> 5;
    int idx = blockIdx.x * 1024 + tid;
    int v = 0;
    if (idx < NN) {
        #pragma unroll
        for (int t = 0; t < NT; t++) v += g_cnt[t * NN + idx];
    }
    int x = v;
    #pragma unroll
    for (int o = 1; o < 32; o <<= 1) {
        int y = __shfl_up_sync(0xFFFFFFFFu, x, o);
        if (lane >= o) x += y;
    }
    if (lane == 31) wsum[w] = x;
    __syncthreads();
    if (w == 0) {
        int s = wsum[lane];
        #pragma unroll
        for (int o = 1; o < 32; o <<= 1) {
            int y = __shfl_up_sync(0xFFFFFFFFu, s, o);
            if (lane >= o) s += y;
        }
        wsum[lane] = s;
    }
    __syncthreads();
    int excl = x - v + (w > 0 ? wsum[w - 1] : 0);
    if (idx < NN) g_off[idx] = excl;
    if (tid == 0) g_bsum[blockIdx.x] = wsum[31];
}
__global__ void scan_bsums() {
    __shared__ int s[64];
    int tid = threadIdx.x;
    s[tid] = (tid < 49) ? g_bsum[tid] : 0;
    __syncthreads();
    #pragma unroll
    for (int o = 1; o < 64; o <<= 1) {
        int v = (tid >= o) ? s[tid - o] : 0;
        __syncthreads();
        s[tid] += v;
        __syncthreads();
    }
    if (tid < 49) g_bsum[tid] = (tid > 0) ? s[tid - 1] : 0;
}
__global__ void add_bsums() {
    int idx = blockIdx.x * 1024 + threadIdx.x;
    if (idx < NN) {
        int o = g_off[idx] + g_bsum[blockIdx.x];
        g_off[idx] = o;
        g_cursor[idx] = o;
    }
}

__global__ void fill_edges(const int* __restrict__ ei, const int* __restrict__ et) {
    int e = blockIdx.x * blockDim.x + threadIdx.x;
    if (e >= NE) return;
    int src = ei[e];
    int dst = ei[NE + e];
    int t = et[e];
    int pos = atomicAdd(&g_cursor[dst], 1);
    g_epk[pos] = (src << 2) | t;
}

// ---------------- mma.sync bf16 GEMM: Y[N,640] = A[N,128] @ W[128,640] --------
// One CTA per 128-row M tile. A (hi/lo) resident; B streamed in 64-col halves,
// SINGLE buffer (102KB smem -> 2 CTAs/SM). Next-B cp.async overlaps epilogue.
// Markidis with 2 independent accumulator sets: hh = Ahi*Bhi, mix = Ahi*Blo+Alo*Bhi.
__device__ __forceinline__ void mma_bf16(float* d, const uint32_t* a, const uint32_t* b) {
    asm volatile("mma.sync.aligned.m16n8k16.row.col.f32.bf16.bf16.f32 "
                 "{%0,%1,%2,%3}, {%4,%5,%6,%7}, {%8,%9}, {%0,%1,%2,%3};"
                 : "+f"(d[0]), "+f"(d[1]), "+f"(d[2]), "+f"(d[3])
                 : "r"(a[0]), "r"(a[1]), "r"(a[2]), "r"(a[3]),
                   "r"(b[0]), "r"(b[1]));
}
__device__ __forceinline__ void ldsm_x4(uint32_t* r, uint32_t saddr) {
    asm volatile("ldmatrix.sync.aligned.m8n8.x4.shared.b16 {%0,%1,%2,%3}, [%4];"
                 : "=r"(r[0]), "=r"(r[1]), "=r"(r[2]), "=r"(r[3]) : "r"(saddr));
}
__device__ __forceinline__ void cp16(void* dst, const void* src) {
    uint32_t d = (uint32_t)__cvta_generic_to_shared(dst);
    asm volatile("cp.async.cg.shared.global [%0], [%1], 16;" :: "r"(d), "l"(src));
}
#define CP_COMMIT() asm volatile("cp.async.commit_group;" ::: "memory")
#define CP_WAIT0()  asm volatile("cp.async.wait_group 0;" ::: "memory")

__global__ __launch_bounds__(256, 2)
void gemm_tc(const __nv_bfloat16* __restrict__ whi, const __nv_bfloat16* __restrict__ wlo,
             const float* __restrict__ bias, float* __restrict__ Y) {
    extern __shared__ __nv_bfloat16 smem[];
    __nv_bfloat16* Ahi = smem;                       // 128 x RS
    __nv_bfloat16* Alo = Ahi + 128 * RS;             // 128 x RS
    __nv_bfloat16* Bh  = Alo + 128 * RS;             // 64 x RS (hi)
    __nv_bfloat16* Bl  = Bh + HALF_N * RS;           // 64 x RS (lo)

    int tid = threadIdx.x, wid = tid >> 5, lane = tid & 31;
    int gid = lane >> 2, tig = lane & 3;
    int l8 = lane & 7, sel = lane >> 3;
    int wm = wid & 3, wn = wid >> 2;                 // warp tile rows wm*32, cols wn*32
    int m0 = blockIdx.x * 128;

    // --- resident A tile (hi/lo), loaded once via cp.async ---
    {
        bool full = (m0 + 128 <= NN);
        #pragma unroll
        for (int i = 0; i < 8; i++) {
            int lin = tid + i * 256;                 // 0..2047
            int r = lin >> 4, c = lin & 15;
            int gr = m0 + r;
            if (full || gr < NN) {
                cp16(Ahi + r * RS + c * 8, g_Ahi + (size_t)gr * F + c * 8);
                cp16(Alo + r * RS + c * 8, g_Alo + (size_t)gr * F + c * 8);
            } else {
                *reinterpret_cast<uint4*>(Ahi + r * RS + c * 8) = make_uint4(0, 0, 0, 0);
                *reinterpret_cast<uint4*>(Alo + r * RS + c * 8) = make_uint4(0, 0, 0, 0);
            }
        }
    }
    // --- B half-tile prefetch (single buffer) ---
    auto issue_B = [&](int s) {
        const __nv_bfloat16* srch = whi + (size_t)s * HALF_N * F;
        const __nv_bfloat16* srcl = wlo + (size_t)s * HALF_N * F;
        #pragma unroll
        for (int i = 0; i < 4; i++) {
            int lin = tid + i * 256;                 // 0..1023
            int r = lin >> 4, c = lin & 15;
            cp16(Bh + r * RS + c * 8, srch + r * F + c * 8);
            cp16(Bl + r * RS + c * 8, srcl + r * F + c * 8);
        }
        CP_COMMIT();
    };
    issue_B(0);

    uint32_t sAhi = (uint32_t)__cvta_generic_to_shared(Ahi);
    uint32_t sAlo = (uint32_t)__cvta_generic_to_shared(Alo);
    uint32_t sBh  = (uint32_t)__cvta_generic_to_shared(Bh);
    uint32_t sBl  = (uint32_t)__cvta_generic_to_shared(Bl);

    int a_r = (sel & 1) * 8 + l8;
    int a_k = (sel >> 1) * 8;
    int b_n = (sel >> 1) * 8 + l8;
    int b_k = (sel & 1) * 8;

    for (int s = 0; s < NHALF; s++) {
        CP_WAIT0();
        __syncthreads();                              // B(s) visible to all warps

        float ahh[2][4][4], amx[2][4][4];
        #pragma unroll
        for (int i = 0; i < 2; i++)
            #pragma unroll
            for (int j = 0; j < 4; j++)
                #pragma unroll
                for (int q = 0; q < 4; q++) { ahh[i][j][q] = 0.f; amx[i][j][q] = 0.f; }

        #pragma unroll
        for (int ks = 0; ks < 8; ks++) {
            int kb = ks * 16;
            uint32_t ah[2][4], al[2][4];
            #pragma unroll
            for (int mf = 0; mf < 2; mf++) {
                uint32_t off = (uint32_t)(((wm * 32 + mf * 16 + a_r) * RS + kb + a_k) * 2);
                ldsm_x4(ah[mf], sAhi + off);
                ldsm_x4(al[mf], sAlo + off);
            }
            uint32_t bh[2][4], bl[2][4];
            #pragma unroll
            for (int g = 0; g < 2; g++) {
                uint32_t off = (uint32_t)(((wn * 32 + g * 16 + b_n) * RS + kb + b_k) * 2);
                ldsm_x4(bh[g], sBh + off);
                ldsm_x4(bl[g], sBl + off);
            }
            #pragma unroll
            for (int mf = 0; mf < 2; mf++)
                #pragma unroll
                for (int g = 0; g < 2; g++) {
                    mma_bf16(ahh[mf][g * 2],     ah[mf], &bh[g][0]);   // hh chain
                    mma_bf16(amx[mf][g * 2],     ah[mf], &bl[g][0]);   // mix chain
                    mma_bf16(ahh[mf][g * 2 + 1], ah[mf], &bh[g][2]);
                    mma_bf16(amx[mf][g * 2 + 1], ah[mf], &bl[g][2]);
                    mma_bf16(amx[mf][g * 2],     al[mf], &bh[g][0]);
                    mma_bf16(amx[mf][g * 2 + 1], al[mf], &bh[g][2]);
                }
        }
        __syncthreads();                              // all warps done reading B(s)
        if (s + 1 < NHALF) issue_B(s + 1);            // async; overlaps epilogue

        // epilogue for this 64-col half: global cols s*64 .. s*64+63
        int gc0 = s * HALF_N;
        bool has_bias = (gc0 < F);
        #pragma unroll
        for (int nf = 0; nf < 4; nf++) {
            int gc = gc0 + wn * 32 + nf * 8 + tig * 2;
            float b0 = has_bias ? bias[gc]     : 0.f;
            float b1 = has_bias ? bias[gc + 1] : 0.f;
            #pragma unroll
            for (int mf = 0; mf < 2; mf++) {
                int row = m0 + wm * 32 + mf * 16 + gid;
                float* base = Y + (size_t)row * NOUT + gc;
                if (row < NN)
                    *reinterpret_cast<float2*>(base) =
                        make_float2(ahh[mf][nf][0] + amx[mf][nf][0] + b0,
                                    ahh[mf][nf][1] + amx[mf][nf][1] + b1);
                if (row + 8 < NN)
                    *reinterpret_cast<float2*>(base + 8 * NOUT) =
                        make_float2(ahh[mf][nf][2] + amx[mf][nf][2] + b0,
                                    ahh[mf][nf][3] + amx[mf][nf][3] + b1);
            }
        }
    }
}

// ---------------- aggregate: out[dst] = Yself[dst] + sum_e invc[t]*Yt[src] ----
// NORM=true: l2norm+relu, then write bf16 hi/lo (layer-2 GEMM input) directly.
template <bool NORM>
__global__ void aggregate(float* __restrict__ outp) {
    int gtid = blockIdx.x * blockDim.x + threadIdx.x;
    int row = gtid >> 5;
    int lane = threadIdx.x & 31;
    if (row >= NN) return;

    float inv[NT];
    #pragma unroll
    for (int t = 0; t < NT; t++) {
        int c = __ldg(&g_cnt[t * NN + row]);
        inv[t] = 1.0f / (float)(c > 1 ? c : 1);
    }
    int beg = g_off[row];
    int end = g_cursor[row];

    float4 acc = *reinterpret_cast<const float4*>(g_Y + (size_t)row * NOUT + lane * 4);

    int i = beg;
    for (; i + 4 <= end; i += 4) {
        int pk0 = __ldg(&g_epk[i]);
        int pk1 = __ldg(&g_epk[i + 1]);
        int pk2 = __ldg(&g_epk[i + 2]);
        int pk3 = __ldg(&g_epk[i + 3]);
        const float4 v0 = *reinterpret_cast<const float4*>(
            g_Y + (size_t)(pk0 >> 2) * NOUT + ((pk0 & 3) + 1) * F + lane * 4);
        const float4 v1 = *reinterpret_cast<const float4*>(
            g_Y + (size_t)(pk1 >> 2) * NOUT + ((pk1 & 3) + 1) * F + lane * 4);
        const float4 v2 = *reinterpret_cast<const float4*>(
            g_Y + (size_t)(pk2 >> 2) * NOUT + ((pk2 & 3) + 1) * F + lane * 4);
        const float4 v3 = *reinterpret_cast<const float4*>(
            g_Y + (size_t)(pk3 >> 2) * NOUT + ((pk3 & 3) + 1) * F + lane * 4);
        float s0 = inv[pk0 & 3], s1 = inv[pk1 & 3], s2 = inv[pk2 & 3], s3 = inv[pk3 & 3];
        acc.x += s0 * v0.x; acc.y += s0 * v0.y; acc.z += s0 * v0.z; acc.w += s0 * v0.w;
        acc.x += s1 * v1.x; acc.y += s1 * v1.y; acc.z += s1 * v1.z; acc.w += s1 * v1.w;
        acc.x += s2 * v2.x; acc.y += s2 * v2.y; acc.z += s2 * v2.z; acc.w += s2 * v2.w;
        acc.x += s3 * v3.x; acc.y += s3 * v3.y; acc.z += s3 * v3.z; acc.w += s3 * v3.w;
    }
    for (; i < end; i++) {
        int pk = __ldg(&g_epk[i]);
        const float4 v = *reinterpret_cast<const float4*>(
            g_Y + (size_t)(pk >> 2) * NOUT + ((pk & 3) + 1) * F + lane * 4);
        float s = inv[pk & 3];
        acc.x += s * v.x; acc.y += s * v.y; acc.z += s * v.z; acc.w += s * v.w;
    }

    if (NORM) {
        float ss = acc.x * acc.x + acc.y * acc.y + acc.z * acc.z + acc.w * acc.w;
        #pragma unroll
        for (int o = 16; o > 0; o >>= 1)
            ss += __shfl_xor_sync(0xFFFFFFFFu, ss, o);
        float invn = 1.0f / fmaxf(sqrtf(ss), 1e-12f);
        acc.x = fmaxf(acc.x * invn, 0.f);
        acc.y = fmaxf(acc.y * invn, 0.f);
        acc.z = fmaxf(acc.z * invn, 0.f);
        acc.w = fmaxf(acc.w * invn, 0.f);
        float f[4] = {acc.x, acc.y, acc.z, acc.w};
        uint32_t hw[2], lw[2];
        #pragma unroll
        for (int j = 0; j < 2; j++) {
            float a = f[2 * j], b = f[2 * j + 1];
            __nv_bfloat16 ha = __float2bfloat16_rn(a);
            __nv_bfloat16 hb = __float2bfloat16_rn(b);
            __nv_bfloat162 hp = __halves2bfloat162(ha, hb);
            __nv_bfloat162 lp = __floats2bfloat162_rn(a - __bfloat162float(ha),
                                                      b - __bfloat162float(hb));
            hw[j] = *reinterpret_cast<uint32_t*>(&hp);
            lw[j] = *reinterpret_cast<uint32_t*>(&lp);
        }
        size_t o = (size_t)row * F + lane * 4;
        *reinterpret_cast<uint2*>(g_Ahi + o) = make_uint2(hw[0], hw[1]);
        *reinterpret_cast<uint2*>(g_Alo + o) = make_uint2(lw[0], lw[1]);
    } else {
        *(reinterpret_cast<float4*>(outp + (size_t)row * F) + lane) = acc;
    }
}

// ---------------- launch -------------------------------------------------------
extern "C" void kernel_launch(void* const* d_in, const int* in_sizes, int n_in,
                              void* d_out, int out_size) {
    const float* x   = (const float*)d_in[0];
    const float* Ws1 = (const float*)d_in[1];
    const float* Wn1 = (const float*)d_in[2];
    const float* b1  = (const float*)d_in[3];
    const float* Ws2 = (const float*)d_in[4];
    const float* Wn2 = (const float*)d_in[5];
    const float* b2  = (const float*)d_in[6];
    const int*   ei  = (const int*)d_in[7];
    const int*   et  = (const int*)d_in[8];
    float* out = (float*)d_out;

    void *p_Y, *p_bb1, *p_bb2, *p_Whi1, *p_Wlo1, *p_Whi2, *p_Wlo2;
    cudaGetSymbolAddress(&p_Y, g_Y);
    cudaGetSymbolAddress(&p_bb1, g_bb1);
    cudaGetSymbolAddress(&p_bb2, g_bb2);
    cudaGetSymbolAddress(&p_Whi1, g_Whi1);
    cudaGetSymbolAddress(&p_Wlo1, g_Wlo1);
    cudaGetSymbolAddress(&p_Whi2, g_Whi2);
    cudaGetSymbolAddress(&p_Wlo2, g_Wlo2);

    // smem: A hi/lo (2*128*RS) + B single-buffered hi/lo half (2*64*RS) = 102KB
    const int SMEM_GEMM = (2 * 128 * RS + 2 * HALF_N * RS) * (int)sizeof(__nv_bfloat16);
    cudaFuncSetAttribute(gemm_tc, cudaFuncAttributeMaxDynamicSharedMemorySize, SMEM_GEMM);

    const int GM_BLOCKS = (NN + 127) / 128;         // 391
    const int AG_BLOCKS = (int)(((size_t)NN * 32 + 255) / 256);
    const int SCAN_BLOCKS = (NN + 1023) / 1024;     // 49
    const int CV_BLOCKS = (int)(((size_t)NN * F / 8 + 255) / 256);

    prep_weights<<<(NOUT * F + 255) / 256, 256>>>(Ws1, Wn1, b1, Ws2, Wn2, b2);  // 1
    convert_bf16<<<CV_BLOCKS, 256>>>(x);                                        // 2
    zero_cnt<<<(NT * NN + 255) / 256, 256>>>();                                 // 3
    gemm_tc<<<GM_BLOCKS, 256, SMEM_GEMM>>>((const __nv_bfloat16*)p_Whi1,        // 4 <- profiled
                                           (const __nv_bfloat16*)p_Wlo1,
                                           (const float*)p_bb1, (float*)p_Y);
    count_edges<<<(NE + 255) / 256, 256>>>(ei, et);                             // 5
    scan_blocks<<<SCAN_BLOCKS, 1024>>>();                                       // 6
    scan_bsums<<<1, 64>>>();                                                    // 7
    add_bsums<<<SCAN_BLOCKS, 1024>>>();                                         // 8
    fill_edges<<<(NE + 255) / 256, 256>>>(ei, et);                              // 9
    aggregate<true><<<AG_BLOCKS, 256>>>(nullptr);                               // 10 (writes Ahi/Alo)

    // ---- layer 2 ----
    gemm_tc<<<GM_BLOCKS, 256, SMEM_GEMM>>>((const __nv_bfloat16*)p_Whi2,        // 11
                                           (const __nv_bfloat16*)p_Wlo2,
                                           (const float*)p_bb2, (float*)p_Y);
    aggregate<false><<<AG_BLOCKS, 256>>>(out);                                  // 12
}